// round 9
// baseline (speedup 1.0000x reference)
#include <cuda_runtime.h>
#include <cuda_bf16.h>
#include <math.h>
#include <stdint.h>

// Problem constants
#define B_ 64
#define S_ 100
#define D_ 1024
#define H_ 16
#define F_ 4096
#define DEPTH_ 64
#define BS_ (B_ * S_)          // 6400
#define N_QKV 3072
#define EPS_ 1e-6f

// ---------------------------------------------------------------------------
// Scratch (device globals; no allocations allowed)
// ---------------------------------------------------------------------------
__device__ float g_pe[S_ * D_];
__device__ float g_x[BS_ * D_];        // full fp32 (residual path)
__device__ float g_xr[BS_ * D_];       // tf32-rounded (GEMM A operand)
__device__ float g_WqkvT[N_QKV * D_];  // [N,K] rounded
__device__ float g_bqkv[N_QKV];
__device__ float g_WoT[D_ * D_];       // [N,K] rounded
__device__ float g_W1T[F_ * D_];       // [N,K] rounded
__device__ float g_W2T[D_ * F_];       // [N,K] rounded
__device__ float g_QKV[BS_ * N_QKV];
__device__ float g_ctx[BS_ * D_];      // rounded at attention epilogue
__device__ float g_t1[2 * BS_ * D_];   // split-K partial buffers
__device__ float g_x1[BS_ * D_];
__device__ float g_x1r[BS_ * D_];
__device__ float g_ffh[BS_ * F_];      // rounded at relu epilogue

__device__ __forceinline__ uint32_t f2tf32(float x) {
    uint32_t r;
    asm("cvt.rna.tf32.f32 %0, %1;" : "=r"(r) : "f"(x));
    return r;
}
__device__ __forceinline__ float roundtf(float x) {
    return __uint_as_float(f2tf32(x));
}

__device__ __forceinline__ void mma_tf32(float* d, const uint32_t* a, const uint32_t* b) {
    asm volatile(
        "mma.sync.aligned.m16n8k8.row.col.f32.tf32.tf32.f32 "
        "{%0,%1,%2,%3}, {%4,%5,%6,%7}, {%8,%9}, {%0,%1,%2,%3};\n"
        : "+f"(d[0]), "+f"(d[1]), "+f"(d[2]), "+f"(d[3])
        : "r"(a[0]), "r"(a[1]), "r"(a[2]), "r"(a[3]), "r"(b[0]), "r"(b[1]));
}

__device__ __forceinline__ void ldsm4(uint32_t* r, uint32_t addr) {
    asm volatile("ldmatrix.sync.aligned.m8n8.x4.shared.b16 {%0,%1,%2,%3}, [%4];"
                 : "=r"(r[0]), "=r"(r[1]), "=r"(r[2]), "=r"(r[3]) : "r"(addr));
}

// ---------------------------------------------------------------------------
// Positional encoding (fp64 to match numpy float64 table)
// ---------------------------------------------------------------------------
__global__ void pe_kernel(float* __restrict__ pe) {
    int idx = blockIdx.x * blockDim.x + threadIdx.x;
    if (idx >= S_ * D_) return;
    int s = idx / D_;
    int d = idx % D_;
    int k2 = d & ~1;
    double div = pow(10000.0, (double)k2 / (double)D_);
    double arg = (double)s / div;
    pe[idx] = (float)((d & 1) ? cos(arg) : sin(arg));
}

// ---------------------------------------------------------------------------
// Embedding gather + positional add; writes fp32 x and tf32-rounded xr
// ---------------------------------------------------------------------------
__global__ void embed_kernel(const int* __restrict__ tokens,
                             const float* __restrict__ emb,
                             const float* __restrict__ pe,
                             float* __restrict__ x, float* __restrict__ xr) {
    int idx = blockIdx.x * blockDim.x + threadIdx.x;
    if (idx >= BS_ * D_ / 4) return;
    int row = idx / (D_ / 4);
    int c4 = idx % (D_ / 4);
    int tok = tokens[row];
    float4 e = ((const float4*)(emb + (size_t)tok * D_))[c4];
    float4 p = ((const float4*)(pe + (size_t)(row % S_) * D_))[c4];
    float4 o;
    o.x = e.x + p.x; o.y = e.y + p.y; o.z = e.z + p.z; o.w = e.w + p.w;
    ((float4*)x)[idx] = o;
    float4 r;
    r.x = roundtf(o.x); r.y = roundtf(o.y); r.z = roundtf(o.z); r.w = roundtf(o.w);
    ((float4*)xr)[idx] = r;
}

// ---------------------------------------------------------------------------
// QKV weight transpose: W{q,k,v}[H,D,64] -> WqkvT[3072, 1024] rounded ([N,K])
// grid(2, 32, 48), block(32, 8)
// ---------------------------------------------------------------------------
__global__ void qkvT_kernel(const float* __restrict__ Wq, const float* __restrict__ Wk,
                            const float* __restrict__ Wv, float* __restrict__ Wt) {
    __shared__ float t[32][33];
    int z = blockIdx.z;
    int which = z / H_, h = z % H_;
    const float* W = (which == 0) ? Wq : ((which == 1) ? Wk : Wv);
    const float* src = W + (size_t)h * D_ * DEPTH_;     // [D, 64]
    int e0 = blockIdx.x * 32, d0 = blockIdx.y * 32;
    int tx = threadIdx.x, ty = threadIdx.y;
    for (int i = ty; i < 32; i += 8)
        t[i][tx] = roundtf(src[(size_t)(d0 + i) * DEPTH_ + e0 + tx]);
    __syncthreads();
    float* dst = Wt + ((size_t)which * D_ + h * DEPTH_) * D_;
    for (int i = ty; i < 32; i += 8)
        dst[(size_t)(e0 + i) * D_ + d0 + tx] = t[tx][i];
}

__global__ void bias_concat(const float* __restrict__ bq, const float* __restrict__ bk,
                            const float* __restrict__ bv, float* __restrict__ bout) {
    int idx = blockIdx.x * blockDim.x + threadIdx.x;
    if (idx >= N_QKV) return;
    int which = idx / D_;
    int n = idx % D_;
    const float* bb = (which == 0) ? bq : ((which == 1) ? bk : bv);
    bout[idx] = bb[n];
}

// ---------------------------------------------------------------------------
// Tiled transpose + tf32 round: src[R,C] -> dst[C,R]. R,C % 32 == 0.
// ---------------------------------------------------------------------------
__global__ void transpose_round(const float* __restrict__ src, float* __restrict__ dst,
                                int R, int C) {
    __shared__ float t[32][33];
    int c0 = blockIdx.x * 32, r0 = blockIdx.y * 32;
    int tx = threadIdx.x, ty = threadIdx.y;
    for (int i = ty; i < 32; i += 8)
        t[i][tx] = roundtf(src[(size_t)(r0 + i) * C + c0 + tx]);
    __syncthreads();
    for (int i = ty; i < 32; i += 8)
        dst[(size_t)(c0 + i) * R + r0 + tx] = t[tx][i];
}

// ---------------------------------------------------------------------------
// TF32 mma.sync GEMM, ldmatrix fragment loads.
// A[M,K] row-major; Bt[N,K] row-major (weights pre-transposed).
// 128x128 CTA tile, 4 warps of 64x64, k-step 32, 2-stage cp.async.
// Both smem tiles 128 rows x 32 cols, stride 44 (conflict-free LDSM).
// Split-K via gridDim.z (raw partial to C + z*M*N; use EPI=0).
// EPI: bit0 bias, bit1 relu, bit2 residual, bit3 round-output.
// ---------------------------------------------------------------------------
#define ASTRIDE 44
#define TILEF (128 * ASTRIDE)           // 5632 floats per operand tile
#define STAGEF (2 * TILEF)              // 11264
#define SMEM_GEMM (2 * STAGEF * 4)      // 90112 bytes

template <int EPI>
__global__ __launch_bounds__(128, 2)
void mma_gemm(const float* __restrict__ A, const float* __restrict__ Bt,
              float* __restrict__ C, const float* __restrict__ bias,
              const float* __restrict__ res, int M, int N, int K) {
    extern __shared__ float smf[];
    int tid = threadIdx.x;
    int lane = tid & 31, warp = tid >> 5;
    int wm = warp & 1, wn = warp >> 1;
    int g = lane >> 2, tg = lane & 3;
    int bm = blockIdx.y * 128, bn = blockIdx.x * 128;

    // Split-K offsets (both operands K-major)
    int kspl = K / gridDim.z;
    int kOff = blockIdx.z * kspl;
    A += kOff;
    Bt += kOff;
    C += (size_t)blockIdx.z * M * N;

    uint32_t smemBase = (uint32_t)__cvta_generic_to_shared(smf);

    float acc[4][8][4];
#pragma unroll
    for (int i = 0; i < 4; i++)
#pragma unroll
        for (int j = 0; j < 8; j++)
#pragma unroll
            for (int c = 0; c < 4; c++) acc[i][j][c] = 0.f;

    const int KT = kspl / 32;

    // Prefetch: both tiles 128 rows x 32 cols (128B/row = 8 x 16B chunks).
    // Per thread: base row = tid>>3 (+q*16), chunk col = (tid&7)*4 floats.
    int pr = tid >> 3, pc = (tid & 7) * 4;
    const float* aSrc = A + (size_t)(bm + pr) * K + pc;
    const float* bSrc = Bt + (size_t)(bn + pr) * K + pc;
    uint32_t aDst0 = smemBase + (uint32_t)(pr * ASTRIDE + pc) * 4;
    uint32_t bDst0 = smemBase + TILEF * 4 + (uint32_t)(pr * ASTRIDE + pc) * 4;

    auto prefetch = [&](int stage) {
        uint32_t so = (uint32_t)(stage * STAGEF * 4);
#pragma unroll
        for (int q = 0; q < 8; q++) {
            uint32_t dst = aDst0 + so + (uint32_t)(q * 16 * ASTRIDE) * 4;
            const float* src = aSrc + (size_t)(q * 16) * K;
            asm volatile("cp.async.cg.shared.global [%0], [%1], 16;" :: "r"(dst), "l"(src));
        }
#pragma unroll
        for (int q = 0; q < 8; q++) {
            uint32_t dst = bDst0 + so + (uint32_t)(q * 16 * ASTRIDE) * 4;
            const float* src = bSrc + (size_t)(q * 16) * K;
            asm volatile("cp.async.cg.shared.global [%0], [%1], 16;" :: "r"(dst), "l"(src));
        }
        aSrc += 32;
        bSrc += 32;
    };

    // ldmatrix per-lane offset: matrix = lane>>3 (mat&1 -> +8 rows,
    // mat>>1 -> +4 cols), row-in-matrix = lane&7. In floats.
    int laneOff = ((((lane >> 3) & 1) * 8 + (lane & 7)) * ASTRIDE) + ((lane >> 4) * 4);

    prefetch(0);
    asm volatile("cp.async.commit_group;");

    for (int kt = 0; kt < KT; kt++) {
        if (kt + 1 < KT) prefetch((kt + 1) & 1);
        asm volatile("cp.async.commit_group;");
        asm volatile("cp.async.wait_group 1;");
        __syncthreads();

        uint32_t sA = smemBase + (uint32_t)((kt & 1) * STAGEF * 4);
        uint32_t sB = sA + TILEF * 4;
#pragma unroll
        for (int ks = 0; ks < 4; ks++) {
            int k0 = ks * 8;
            uint32_t afr[4][4];
#pragma unroll
            for (int mi = 0; mi < 4; mi++)
                ldsm4(afr[mi], sA + (uint32_t)(((wm * 64 + mi * 16) * ASTRIDE) + k0 + laneOff) * 4);
            uint32_t bfr[8][2];
#pragma unroll
            for (int nj = 0; nj < 4; nj++) {
                uint32_t t[4];
                ldsm4(t, sB + (uint32_t)(((wn * 64 + nj * 16) * ASTRIDE) + k0 + laneOff) * 4);
                bfr[2 * nj][0] = t[0];
                bfr[2 * nj][1] = t[2];
                bfr[2 * nj + 1][0] = t[1];
                bfr[2 * nj + 1][1] = t[3];
            }
#pragma unroll
            for (int mi = 0; mi < 4; mi++)
#pragma unroll
                for (int ni = 0; ni < 8; ni++)
                    mma_tf32(acc[mi][ni], afr[mi], bfr[ni]);
        }
        __syncthreads();
    }

#pragma unroll
    for (int mi = 0; mi < 4; mi++) {
#pragma unroll
        for (int rr = 0; rr < 2; rr++) {
            int row = bm + wm * 64 + mi * 16 + rr * 8 + g;
#pragma unroll
            for (int ni = 0; ni < 8; ni++) {
                int col = bn + wn * 64 + ni * 8 + tg * 2;
                float vx = acc[mi][ni][rr * 2 + 0];
                float vy = acc[mi][ni][rr * 2 + 1];
                if (EPI & 1) { vx += bias[col]; vy += bias[col + 1]; }
                if (EPI & 4) {
                    const float* rp = res + (size_t)row * N + col;
                    vx += rp[0]; vy += rp[1];
                }
                if (EPI & 2) { vx = fmaxf(vx, 0.f); vy = fmaxf(vy, 0.f); }
                if (EPI & 8) { vx = roundtf(vx); vy = roundtf(vy); }
                *(float2*)&C[(size_t)row * N + col] = make_float2(vx, vy);
            }
        }
    }
}

// ---------------------------------------------------------------------------
// Fused attention per (b, h) — tensor-core QK^T and AV via mma.sync tf32.
// ---------------------------------------------------------------------------
#define QS_STR 76
#define KT_STR 104
#define VS_STR 72
#define SC_STR 108
#define QROWS 112
#define VROWS 104
#define SROWS 112
#define ATT_FLOATS (QROWS * QS_STR + DEPTH_ * KT_STR + VROWS * VS_STR + SROWS * SC_STR)
#define ATT_SMEM (ATT_FLOATS * 4)

__global__ __launch_bounds__(256)
void attention_kernel(const float* __restrict__ QKV, float* __restrict__ ctx) {
    extern __shared__ float sm[];
    float* qs = sm;
    float* kt = qs + QROWS * QS_STR;
    float* vs = kt + DEPTH_ * KT_STR;
    float* sc = vs + VROWS * VS_STR;

    int bh = blockIdx.x;
    int b = bh / H_;
    int h = bh % H_;
    int tid = threadIdx.x;
    int lane = tid & 31, warp = tid >> 5;
    int g = lane >> 2, tg = lane & 3;

    for (int i = tid; i < ATT_FLOATS; i += 256) sm[i] = 0.f;
    __syncthreads();

    for (int i = tid; i < S_ * (DEPTH_ / 4); i += 256) {
        int s = i >> 4, e4 = (i & 15) * 4;
        size_t off = ((size_t)(b * S_ + s)) * N_QKV + h * DEPTH_ + e4;
        float4 q = *(const float4*)(QKV + off);
        float4 k = *(const float4*)(QKV + off + D_);
        float4 v = *(const float4*)(QKV + off + 2 * D_);
        qs[s * QS_STR + e4 + 0] = roundtf(q.x);
        qs[s * QS_STR + e4 + 1] = roundtf(q.y);
        qs[s * QS_STR + e4 + 2] = roundtf(q.z);
        qs[s * QS_STR + e4 + 3] = roundtf(q.w);
        kt[(e4 + 0) * KT_STR + s] = roundtf(k.x);
        kt[(e4 + 1) * KT_STR + s] = roundtf(k.y);
        kt[(e4 + 2) * KT_STR + s] = roundtf(k.z);
        kt[(e4 + 3) * KT_STR + s] = roundtf(k.w);
        float4 vr = make_float4(roundtf(v.x), roundtf(v.y), roundtf(v.z), roundtf(v.w));
        *(float4*)&vs[s * VS_STR + e4] = vr;
    }
    __syncthreads();

    if (warp < 7) {
        float acc[13][4];
#pragma unroll
        for (int ni = 0; ni < 13; ni++)
#pragma unroll
            for (int c = 0; c < 4; c++) acc[ni][c] = 0.f;
        const uint32_t* qsu = (const uint32_t*)qs;
        const uint32_t* ktu = (const uint32_t*)kt;
        int m = warp * 16 + g;
#pragma unroll
        for (int ks = 0; ks < 8; ks++) {
            int k0 = ks * 8;
            uint32_t a[4];
            a[0] = qsu[m * QS_STR + k0 + tg];
            a[1] = qsu[(m + 8) * QS_STR + k0 + tg];
            a[2] = qsu[m * QS_STR + k0 + tg + 4];
            a[3] = qsu[(m + 8) * QS_STR + k0 + tg + 4];
#pragma unroll
            for (int ni = 0; ni < 13; ni++) {
                uint32_t bf[2];
                bf[0] = ktu[(k0 + tg) * KT_STR + ni * 8 + g];
                bf[1] = ktu[(k0 + tg + 4) * KT_STR + ni * 8 + g];
                mma_tf32(acc[ni], a, bf);
            }
        }
        const float scale = 0.125f;
#pragma unroll
        for (int ni = 0; ni < 13; ni++)
#pragma unroll
            for (int rr = 0; rr < 2; rr++) {
                int row = warp * 16 + rr * 8 + g;
                int col = ni * 8 + tg * 2;
                *(float2*)&sc[row * SC_STR + col] =
                    make_float2(acc[ni][rr * 2] * scale, acc[ni][rr * 2 + 1] * scale);
            }
    }
    __syncthreads();

    for (int r = warp; r < S_; r += 8) {
        float v0 = (lane < S_) ? sc[r * SC_STR + lane] : -1e30f;
        float v1 = sc[r * SC_STR + lane + 32];
        float v2 = (lane + 64 < S_) ? sc[r * SC_STR + lane + 64] : -1e30f;
        float v3 = (lane + 96 < S_) ? sc[r * SC_STR + lane + 96] : -1e30f;
        float m = fmaxf(fmaxf(v0, v1), fmaxf(v2, v3));
#pragma unroll
        for (int off = 16; off > 0; off >>= 1)
            m = fmaxf(m, __shfl_xor_sync(0xffffffffu, m, off));
        float e0 = (lane < S_) ? __expf(v0 - m) : 0.f;
        float e1 = __expf(v1 - m);
        float e2 = (lane + 64 < S_) ? __expf(v2 - m) : 0.f;
        float e3 = (lane + 96 < S_) ? __expf(v3 - m) : 0.f;
        float s = e0 + e1 + e2 + e3;
#pragma unroll
        for (int off = 16; off > 0; off >>= 1)
            s += __shfl_xor_sync(0xffffffffu, s, off);
        float inv = 1.f / s;
        if (lane < S_) sc[r * SC_STR + lane] = roundtf(e0 * inv);
        sc[r * SC_STR + lane + 32] = roundtf(e1 * inv);
        if (lane + 64 < S_) sc[r * SC_STR + lane + 64] = roundtf(e2 * inv);
        if (lane + 96 < S_) sc[r * SC_STR + lane + 96] = roundtf(e3 * inv);
    }
    __syncthreads();

    if (warp < 7) {
        float acc[8][4];
#pragma unroll
        for (int ni = 0; ni < 8; ni++)
#pragma unroll
            for (int c = 0; c < 4; c++) acc[ni][c] = 0.f;
        const uint32_t* scu = (const uint32_t*)sc;
        const uint32_t* vsu = (const uint32_t*)vs;
        int m = warp * 16 + g;
#pragma unroll
        for (int ks = 0; ks < 13; ks++) {
            int k0 = ks * 8;
            uint32_t a[4];
            a[0] = scu[m * SC_STR + k0 + tg];
            a[1] = scu[(m + 8) * SC_STR + k0 + tg];
            a[2] = scu[m * SC_STR + k0 + tg + 4];
            a[3] = scu[(m + 8) * SC_STR + k0 + tg + 4];
#pragma unroll
            for (int ni = 0; ni < 8; ni++) {
                uint32_t bf[2];
                bf[0] = vsu[(k0 + tg) * VS_STR + ni * 8 + g];
                bf[1] = vsu[(k0 + tg + 4) * VS_STR + ni * 8 + g];
                mma_tf32(acc[ni], a, bf);
            }
        }
        const size_t cbase = (size_t)b * S_ * D_ + (size_t)h * DEPTH_;
#pragma unroll
        for (int ni = 0; ni < 8; ni++)
#pragma unroll
            for (int rr = 0; rr < 2; rr++) {
                int row = warp * 16 + rr * 8 + g;
                if (row < S_) {
                    int col = ni * 8 + tg * 2;
                    *(float2*)&ctx[cbase + (size_t)row * D_ + col] =
                        make_float2(roundtf(acc[ni][rr * 2]), roundtf(acc[ni][rr * 2 + 1]));
                }
            }
    }
}

// ---------------------------------------------------------------------------
// Fused split-K reduce + bias + residual + LayerNorm.
// ---------------------------------------------------------------------------
template <bool ROUND2>
__global__ __launch_bounds__(256)
void lnred_kernel(const float* __restrict__ p0, const float* __restrict__ p1,
                  const float* __restrict__ bias, const float* __restrict__ res,
                  const float* __restrict__ gamma, const float* __restrict__ beta,
                  float* __restrict__ out, float* __restrict__ out_r) {
    int row = blockIdx.x;
    size_t base = (size_t)row * D_;
    int tid = threadIdx.x;

    float vals[4];
    float sum = 0.f, sq = 0.f;
#pragma unroll
    for (int r = 0; r < 4; r++) {
        int d = tid + r * 256;
        float v = p0[base + d] + p1[base + d] + bias[d] + res[base + d];
        vals[r] = v;
        sum += v;
        sq += v * v;
    }
#pragma unroll
    for (int off = 16; off > 0; off >>= 1) {
        sum += __shfl_xor_sync(0xffffffffu, sum, off);
        sq += __shfl_xor_sync(0xffffffffu, sq, off);
    }
    __shared__ float s1[8], s2[8];
    int wid = tid >> 5, lid = tid & 31;
    if (lid == 0) { s1[wid] = sum; s2[wid] = sq; }
    __syncthreads();
    if (wid == 0) {
        sum = (lid < 8) ? s1[lid] : 0.f;
        sq = (lid < 8) ? s2[lid] : 0.f;
#pragma unroll
        for (int off = 4; off > 0; off >>= 1) {
            sum += __shfl_xor_sync(0xffffffffu, sum, off);
            sq += __shfl_xor_sync(0xffffffffu, sq, off);
        }
        if (lid == 0) { s1[0] = sum; s2[0] = sq; }
    }
    __syncthreads();
    float mean = s1[0] * (1.0f / D_);
    float var = s2[0] * (1.0f / D_) - mean * mean;
    float inv = rsqrtf(var + EPS_);
#pragma unroll
    for (int r = 0; r < 4; r++) {
        int d = tid + r * 256;
        float o = gamma[d] * ((vals[r] - mean) * inv) + beta[d];
        out[base + d] = o;
        if (ROUND2) out_r[base + d] = roundtf(o);
    }
}

// ---------------------------------------------------------------------------
// Launch
// ---------------------------------------------------------------------------
extern "C" void kernel_launch(void* const* d_in, const int* in_sizes, int n_in,
                              void* d_out, int out_size) {
    const int* tokens = (const int*)d_in[0];
    const float* emb = (const float*)d_in[1];
    const float* Wq = (const float*)d_in[2];
    const float* bq = (const float*)d_in[3];
    const float* Wk = (const float*)d_in[4];
    const float* bk = (const float*)d_in[5];
    const float* Wv = (const float*)d_in[6];
    const float* bv = (const float*)d_in[7];
    const float* Wo = (const float*)d_in[8];
    const float* bo = (const float*)d_in[9];
    const float* W1 = (const float*)d_in[10];
    const float* b1 = (const float*)d_in[11];
    const float* W2 = (const float*)d_in[12];
    const float* b2 = (const float*)d_in[13];
    const float* gamma1 = (const float*)d_in[14];
    const float* beta1 = (const float*)d_in[15];
    const float* gamma2 = (const float*)d_in[16];
    const float* beta2 = (const float*)d_in[17];
    float* out = (float*)d_out;

    float *pe, *x, *xr, *WqkvT, *bqkv, *WoT, *W1T, *W2T, *QKV, *ctx, *t1, *x1, *x1r, *ffh;
    cudaGetSymbolAddress((void**)&pe, g_pe);
    cudaGetSymbolAddress((void**)&x, g_x);
    cudaGetSymbolAddress((void**)&xr, g_xr);
    cudaGetSymbolAddress((void**)&WqkvT, g_WqkvT);
    cudaGetSymbolAddress((void**)&bqkv, g_bqkv);
    cudaGetSymbolAddress((void**)&WoT, g_WoT);
    cudaGetSymbolAddress((void**)&W1T, g_W1T);
    cudaGetSymbolAddress((void**)&W2T, g_W2T);
    cudaGetSymbolAddress((void**)&QKV, g_QKV);
    cudaGetSymbolAddress((void**)&ctx, g_ctx);
    cudaGetSymbolAddress((void**)&t1, g_t1);
    cudaGetSymbolAddress((void**)&x1, g_x1);
    cudaGetSymbolAddress((void**)&x1r, g_x1r);
    cudaGetSymbolAddress((void**)&ffh, g_ffh);

    cudaFuncSetAttribute(attention_kernel,
                         cudaFuncAttributeMaxDynamicSharedMemorySize, ATT_SMEM);
    cudaFuncSetAttribute(mma_gemm<0>,
                         cudaFuncAttributeMaxDynamicSharedMemorySize, SMEM_GEMM);
    cudaFuncSetAttribute(mma_gemm<1>,
                         cudaFuncAttributeMaxDynamicSharedMemorySize, SMEM_GEMM);
    cudaFuncSetAttribute(mma_gemm<11>,
                         cudaFuncAttributeMaxDynamicSharedMemorySize, SMEM_GEMM);

    // 1. positional encoding + embedding (+ rounded twin)
    pe_kernel<<<(S_ * D_ + 255) / 256, 256>>>(pe);
    embed_kernel<<<(BS_ * D_ / 4 + 255) / 256, 256>>>(tokens, emb, pe, x, xr);

    // 2. weight prep: transposed [N,K] + rounded
    qkvT_kernel<<<dim3(2, 32, 48), dim3(32, 8)>>>(Wq, Wk, Wv, WqkvT);
    bias_concat<<<(N_QKV + 255) / 256, 256>>>(bq, bk, bv, bqkv);
    transpose_round<<<dim3(32, 32), dim3(32, 8)>>>(Wo, WoT, D_, D_);
    transpose_round<<<dim3(128, 32), dim3(32, 8)>>>(W1, W1T, D_, F_);
    transpose_round<<<dim3(32, 128), dim3(32, 8)>>>(W2, W2T, F_, D_);

    // 3. fused QKV projection
    mma_gemm<1><<<dim3(N_QKV / 128, BS_ / 128), 128, SMEM_GEMM>>>(
        xr, WqkvT, QKV, bqkv, nullptr, BS_, N_QKV, D_);

    // 4. attention (tensor-core QK + AV; rounds ctx)
    attention_kernel<<<B_ * H_, 256, ATT_SMEM>>>(QKV, ctx);

    // 5. output projection (split-K 2, raw partials) + fused reduce+LN1
    mma_gemm<0><<<dim3(D_ / 128, BS_ / 128, 2), 128, SMEM_GEMM>>>(
        ctx, WoT, t1, nullptr, nullptr, BS_, D_, D_);
    lnred_kernel<true><<<BS_, 256>>>(t1, t1 + (size_t)BS_ * D_, bo, x,
                                     gamma1, beta1, x1, x1r);

    // 6. FFN: W1 (bias+relu+round epilogue), W2 (split-K 2, raw partials)
    mma_gemm<11><<<dim3(F_ / 128, BS_ / 128), 128, SMEM_GEMM>>>(
        x1r, W1T, ffh, b1, nullptr, BS_, F_, D_);
    mma_gemm<0><<<dim3(D_ / 128, BS_ / 128, 2), 128, SMEM_GEMM>>>(
        ffh, W2T, t1, nullptr, nullptr, BS_, D_, F_);

    // 7. fused reduce + LN2 -> output
    lnred_kernel<false><<<BS_, 256>>>(t1, t1 + (size_t)BS_ * D_, b2, x1,
                                      gamma2, beta2, out, nullptr);
}

// round 10
// speedup vs baseline: 1.7546x; 1.7546x over previous
#include <cuda_runtime.h>
#include <cuda_bf16.h>
#include <math.h>
#include <stdint.h>

// Problem constants
#define B_ 64
#define S_ 100
#define D_ 1024
#define H_ 16
#define F_ 4096
#define DEPTH_ 64
#define BS_ (B_ * S_)          // 6400
#define N_QKV 3072
#define EPS_ 1e-6f

// ---------------------------------------------------------------------------
// Scratch (device globals; no allocations allowed)
// ---------------------------------------------------------------------------
__device__ float g_pe[S_ * D_];
__device__ float g_x[BS_ * D_];      // full fp32 (residual path)
__device__ float g_xr[BS_ * D_];     // tf32-rounded (GEMM A operand)
__device__ float g_Wqkv[D_ * N_QKV]; // rounded, [K,N]
__device__ float g_bqkv[N_QKV];
__device__ float g_Wor[D_ * D_];     // rounded Wo [K,N]
__device__ float g_W1r[D_ * F_];     // rounded W1 [K,N]
__device__ float g_W2r[F_ * D_];     // rounded W2 [K,N]
__device__ float g_QKV[BS_ * N_QKV];
__device__ float g_ctx[BS_ * D_];    // rounded at attention epilogue
__device__ float g_t1[2 * BS_ * D_]; // split-K partial buffers
__device__ float g_x1[BS_ * D_];
__device__ float g_x1r[BS_ * D_];
__device__ float g_ffh[BS_ * F_];    // rounded at relu epilogue

__device__ __forceinline__ uint32_t f2tf32(float x) {
    uint32_t r;
    asm("cvt.rna.tf32.f32 %0, %1;" : "=r"(r) : "f"(x));
    return r;
}
__device__ __forceinline__ float roundtf(float x) {
    return __uint_as_float(f2tf32(x));
}

__device__ __forceinline__ void mma_tf32(float* d, const uint32_t* a, const uint32_t* b) {
    asm volatile(
        "mma.sync.aligned.m16n8k8.row.col.f32.tf32.tf32.f32 "
        "{%0,%1,%2,%3}, {%4,%5,%6,%7}, {%8,%9}, {%0,%1,%2,%3};\n"
        : "+f"(d[0]), "+f"(d[1]), "+f"(d[2]), "+f"(d[3])
        : "r"(a[0]), "r"(a[1]), "r"(a[2]), "r"(a[3]), "r"(b[0]), "r"(b[1]));
}

// ---------------------------------------------------------------------------
// Positional encoding (fp64 to match numpy float64 table)
// ---------------------------------------------------------------------------
__global__ void pe_kernel(float* __restrict__ pe) {
    int idx = blockIdx.x * blockDim.x + threadIdx.x;
    if (idx >= S_ * D_) return;
    int s = idx / D_;
    int d = idx % D_;
    int k2 = d & ~1;
    double div = pow(10000.0, (double)k2 / (double)D_);
    double arg = (double)s / div;
    pe[idx] = (float)((d & 1) ? cos(arg) : sin(arg));
}

// ---------------------------------------------------------------------------
// Embedding gather + positional add; writes fp32 x and tf32-rounded xr
// ---------------------------------------------------------------------------
__global__ void embed_kernel(const int* __restrict__ tokens,
                             const float* __restrict__ emb,
                             const float* __restrict__ pe,
                             float* __restrict__ x, float* __restrict__ xr) {
    int idx = blockIdx.x * blockDim.x + threadIdx.x;
    if (idx >= BS_ * D_ / 4) return;
    int row = idx / (D_ / 4);
    int c4 = idx % (D_ / 4);
    int tok = tokens[row];
    float4 e = ((const float4*)(emb + (size_t)tok * D_))[c4];
    float4 p = ((const float4*)(pe + (size_t)(row % S_) * D_))[c4];
    float4 o;
    o.x = e.x + p.x; o.y = e.y + p.y; o.z = e.z + p.z; o.w = e.w + p.w;
    ((float4*)x)[idx] = o;
    float4 r;
    r.x = roundtf(o.x); r.y = roundtf(o.y); r.z = roundtf(o.z); r.w = roundtf(o.w);
    ((float4*)xr)[idx] = r;
}

// ---------------------------------------------------------------------------
// Permute Wq/Wk/Wv [H,D,64] -> combined [D, 3072] (rounded); biases -> [3072]
// ---------------------------------------------------------------------------
__global__ void permute_qkv_kernel(const float* __restrict__ Wq, const float* __restrict__ Wk,
                                   const float* __restrict__ Wv,
                                   const float* __restrict__ bq, const float* __restrict__ bk,
                                   const float* __restrict__ bv,
                                   float* __restrict__ Wout, float* __restrict__ bout) {
    int idx = blockIdx.x * blockDim.x + threadIdx.x;
    const int total = 3 * D_ * D_;
    if (idx < total) {
        int which = idx / (D_ * D_);
        int r = idx % (D_ * D_);
        int d = r / D_;
        int n = r % D_;
        int h = n >> 6, e = n & 63;
        const float* W = (which == 0) ? Wq : ((which == 1) ? Wk : Wv);
        Wout[(size_t)d * N_QKV + which * D_ + n] =
            roundtf(W[((size_t)h * D_ + d) * DEPTH_ + e]);
    }
    if (idx < N_QKV) {
        int which = idx / D_;
        int n = idx % D_;
        const float* bb = (which == 0) ? bq : ((which == 1) ? bk : bv);
        bout[idx] = bb[n];
    }
}

// ---------------------------------------------------------------------------
// Combined tf32 round-copy of Wo, W1, W2 in one launch.
// ---------------------------------------------------------------------------
#define N4_WO (D_ * D_ / 4)
#define N4_W1 (D_ * F_ / 4)
#define N4_W2 (F_ * D_ / 4)
__global__ void roundcpy3_kernel(const float* __restrict__ Wo, float* __restrict__ WoR,
                                 const float* __restrict__ W1, float* __restrict__ W1R,
                                 const float* __restrict__ W2, float* __restrict__ W2R) {
    int idx = blockIdx.x * blockDim.x + threadIdx.x;
    const float* in;
    float* out;
    int off;
    if (idx < N4_WO) { in = Wo; out = WoR; off = idx; }
    else if (idx < N4_WO + N4_W1) { in = W1; out = W1R; off = idx - N4_WO; }
    else if (idx < N4_WO + N4_W1 + N4_W2) { in = W2; out = W2R; off = idx - N4_WO - N4_W1; }
    else return;
    float4 v = ((const float4*)in)[off];
    float4 r;
    r.x = roundtf(v.x); r.y = roundtf(v.y); r.z = roundtf(v.z); r.w = roundtf(v.w);
    ((float4*)out)[off] = r;
}

// ---------------------------------------------------------------------------
// TF32 mma.sync GEMM. 128x128 CTA tile, 4 warps of 64x64, k-step 32,
// cp.async double buffer. ASTRIDE=36 shrinks smem to 70KB -> 3 CTAs/SM.
// Split-K via gridDim.z (raw partial to C + z*M*N; EPI must be 0).
// EPI: bit0 bias, bit1 relu, bit2 residual, bit3 round-output.
// ---------------------------------------------------------------------------
#define ASTRIDE 36                       // banks 4g+tg all distinct
#define BSTRIDE 136                      // banks 8tg+g all distinct
#define AFLOATS (128 * ASTRIDE)          // 4608
#define BFLOATS (32 * BSTRIDE)           // 4352
#define STAGEF  (AFLOATS + BFLOATS)      // 8960
#define SMEM_GEMM (2 * STAGEF * 4)       // 71680 -> 3 CTAs/SM

template <int EPI>
__global__ __launch_bounds__(128, 3)
void mma_gemm(const float* __restrict__ A, const float* __restrict__ Bm,
              float* __restrict__ C, const float* __restrict__ bias,
              const float* __restrict__ res, int M, int N, int K) {
    extern __shared__ float smf[];
    int tid = threadIdx.x;
    int lane = tid & 31, warp = tid >> 5;
    int wm = warp & 1, wn = warp >> 1;
    int g = lane >> 2, tg = lane & 3;
    int bm = blockIdx.y * 128, bn = blockIdx.x * 128;

    // Split-K offsets
    int kspl = K / gridDim.z;
    int kOff = blockIdx.z * kspl;
    A += kOff;
    Bm += (size_t)kOff * N;
    C += (size_t)blockIdx.z * M * N;

    uint32_t smemBase = (uint32_t)__cvta_generic_to_shared(smf);

    float acc[4][8][4];
#pragma unroll
    for (int i = 0; i < 4; i++)
#pragma unroll
        for (int j = 0; j < 8; j++)
#pragma unroll
            for (int c = 0; c < 4; c++) acc[i][j][c] = 0.f;

    const int KT = kspl / 32;

    // Prefetch geometry (128 threads):
    // A tile 128x32: chunk c = q*128+tid, row = tid>>3 (+q*16), col=(tid&7)*4
    // B tile 32x128: krow = tid>>5 (+q*4), col=(tid&31)*4
    int aRow = tid >> 3, aColv = tid & 7;
    int bKrow = tid >> 5, bColv = tid & 31;
    const float* aSrc = A + (size_t)(bm + aRow) * K + aColv * 4;
    const float* bSrc = Bm + (size_t)bKrow * N + bn + bColv * 4;
    uint32_t aDst0 = smemBase + (uint32_t)(aRow * ASTRIDE + aColv * 4) * 4;
    uint32_t bDst0 = smemBase + AFLOATS * 4 + (uint32_t)(bKrow * BSTRIDE + bColv * 4) * 4;

    auto prefetch = [&](int stage) {
        uint32_t so = (uint32_t)(stage * STAGEF * 4);
#pragma unroll
        for (int q = 0; q < 8; q++) {
            uint32_t dst = aDst0 + so + (uint32_t)(q * 16 * ASTRIDE) * 4;
            const float* src = aSrc + (size_t)(q * 16) * K;
            asm volatile("cp.async.cg.shared.global [%0], [%1], 16;" :: "r"(dst), "l"(src));
        }
#pragma unroll
        for (int q = 0; q < 8; q++) {
            uint32_t dst = bDst0 + so + (uint32_t)(q * 4 * BSTRIDE) * 4;
            const float* src = bSrc + (size_t)(q * 4) * N;
            asm volatile("cp.async.cg.shared.global [%0], [%1], 16;" :: "r"(dst), "l"(src));
        }
        aSrc += 32;
        bSrc += (size_t)32 * N;
    };

    prefetch(0);
    asm volatile("cp.async.commit_group;");

    for (int kt = 0; kt < KT; kt++) {
        if (kt + 1 < KT) prefetch((kt + 1) & 1);
        asm volatile("cp.async.commit_group;");
        asm volatile("cp.async.wait_group 1;");
        __syncthreads();

        const uint32_t* As = (const uint32_t*)(smf + (kt & 1) * STAGEF);
        const uint32_t* Bs = As + AFLOATS;
#pragma unroll
        for (int ks = 0; ks < 4; ks++) {
            int k0 = ks * 8;
            uint32_t afr[4][4];
#pragma unroll
            for (int mi = 0; mi < 4; mi++) {
                int m = wm * 64 + mi * 16 + g;
                afr[mi][0] = As[m * ASTRIDE + k0 + tg];
                afr[mi][1] = As[(m + 8) * ASTRIDE + k0 + tg];
                afr[mi][2] = As[m * ASTRIDE + k0 + tg + 4];
                afr[mi][3] = As[(m + 8) * ASTRIDE + k0 + tg + 4];
            }
            uint32_t bfr[8][2];
#pragma unroll
            for (int ni = 0; ni < 8; ni++) {
                int n = wn * 64 + ni * 8 + g;
                bfr[ni][0] = Bs[(k0 + tg) * BSTRIDE + n];
                bfr[ni][1] = Bs[(k0 + tg + 4) * BSTRIDE + n];
            }
#pragma unroll
            for (int mi = 0; mi < 4; mi++)
#pragma unroll
                for (int ni = 0; ni < 8; ni++)
                    mma_tf32(acc[mi][ni], afr[mi], bfr[ni]);
        }
        __syncthreads();
    }

#pragma unroll
    for (int mi = 0; mi < 4; mi++) {
#pragma unroll
        for (int rr = 0; rr < 2; rr++) {
            int row = bm + wm * 64 + mi * 16 + rr * 8 + g;
#pragma unroll
            for (int ni = 0; ni < 8; ni++) {
                int col = bn + wn * 64 + ni * 8 + tg * 2;
                float vx = acc[mi][ni][rr * 2 + 0];
                float vy = acc[mi][ni][rr * 2 + 1];
                if (EPI & 1) { vx += bias[col]; vy += bias[col + 1]; }
                if (EPI & 4) {
                    const float* rp = res + (size_t)row * N + col;
                    vx += rp[0]; vy += rp[1];
                }
                if (EPI & 2) { vx = fmaxf(vx, 0.f); vy = fmaxf(vy, 0.f); }
                if (EPI & 8) { vx = roundtf(vx); vy = roundtf(vy); }
                *(float2*)&C[(size_t)row * N + col] = make_float2(vx, vy);
            }
        }
    }
}

// ---------------------------------------------------------------------------
// Fused attention per (b, h) — tensor-core QK^T and AV via mma.sync tf32.
// ---------------------------------------------------------------------------
#define QS_STR 76
#define KT_STR 104
#define VS_STR 72
#define SC_STR 108
#define QROWS 112
#define VROWS 104
#define SROWS 112
#define ATT_FLOATS (QROWS * QS_STR + DEPTH_ * KT_STR + VROWS * VS_STR + SROWS * SC_STR)
#define ATT_SMEM (ATT_FLOATS * 4)

__global__ __launch_bounds__(256)
void attention_kernel(const float* __restrict__ QKV, float* __restrict__ ctx) {
    extern __shared__ float sm[];
    float* qs = sm;
    float* kt = qs + QROWS * QS_STR;
    float* vs = kt + DEPTH_ * KT_STR;
    float* sc = vs + VROWS * VS_STR;

    int bh = blockIdx.x;
    int b = bh / H_;
    int h = bh % H_;
    int tid = threadIdx.x;
    int lane = tid & 31, warp = tid >> 5;
    int g = lane >> 2, tg = lane & 3;

    for (int i = tid; i < ATT_FLOATS; i += 256) sm[i] = 0.f;
    __syncthreads();

    for (int i = tid; i < S_ * (DEPTH_ / 4); i += 256) {
        int s = i >> 4, e4 = (i & 15) * 4;
        size_t off = ((size_t)(b * S_ + s)) * N_QKV + h * DEPTH_ + e4;
        float4 q = *(const float4*)(QKV + off);
        float4 k = *(const float4*)(QKV + off + D_);
        float4 v = *(const float4*)(QKV + off + 2 * D_);
        qs[s * QS_STR + e4 + 0] = roundtf(q.x);
        qs[s * QS_STR + e4 + 1] = roundtf(q.y);
        qs[s * QS_STR + e4 + 2] = roundtf(q.z);
        qs[s * QS_STR + e4 + 3] = roundtf(q.w);
        kt[(e4 + 0) * KT_STR + s] = roundtf(k.x);
        kt[(e4 + 1) * KT_STR + s] = roundtf(k.y);
        kt[(e4 + 2) * KT_STR + s] = roundtf(k.z);
        kt[(e4 + 3) * KT_STR + s] = roundtf(k.w);
        float4 vr = make_float4(roundtf(v.x), roundtf(v.y), roundtf(v.z), roundtf(v.w));
        *(float4*)&vs[s * VS_STR + e4] = vr;
    }
    __syncthreads();

    if (warp < 7) {
        float acc[13][4];
#pragma unroll
        for (int ni = 0; ni < 13; ni++)
#pragma unroll
            for (int c = 0; c < 4; c++) acc[ni][c] = 0.f;
        const uint32_t* qsu = (const uint32_t*)qs;
        const uint32_t* ktu = (const uint32_t*)kt;
        int m = warp * 16 + g;
#pragma unroll
        for (int ks = 0; ks < 8; ks++) {
            int k0 = ks * 8;
            uint32_t a[4];
            a[0] = qsu[m * QS_STR + k0 + tg];
            a[1] = qsu[(m + 8) * QS_STR + k0 + tg];
            a[2] = qsu[m * QS_STR + k0 + tg + 4];
            a[3] = qsu[(m + 8) * QS_STR + k0 + tg + 4];
#pragma unroll
            for (int ni = 0; ni < 13; ni++) {
                uint32_t bf[2];
                bf[0] = ktu[(k0 + tg) * KT_STR + ni * 8 + g];
                bf[1] = ktu[(k0 + tg + 4) * KT_STR + ni * 8 + g];
                mma_tf32(acc[ni], a, bf);
            }
        }
        const float scale = 0.125f;
#pragma unroll
        for (int ni = 0; ni < 13; ni++)
#pragma unroll
            for (int rr = 0; rr < 2; rr++) {
                int row = warp * 16 + rr * 8 + g;
                int col = ni * 8 + tg * 2;
                *(float2*)&sc[row * SC_STR + col] =
                    make_float2(acc[ni][rr * 2] * scale, acc[ni][rr * 2 + 1] * scale);
            }
    }
    __syncthreads();

    for (int r = warp; r < S_; r += 8) {
        float v0 = (lane < S_) ? sc[r * SC_STR + lane] : -1e30f;
        float v1 = sc[r * SC_STR + lane + 32];
        float v2 = (lane + 64 < S_) ? sc[r * SC_STR + lane + 64] : -1e30f;
        float v3 = (lane + 96 < S_) ? sc[r * SC_STR + lane + 96] : -1e30f;
        float m = fmaxf(fmaxf(v0, v1), fmaxf(v2, v3));
#pragma unroll
        for (int off = 16; off > 0; off >>= 1)
            m = fmaxf(m, __shfl_xor_sync(0xffffffffu, m, off));
        float e0 = (lane < S_) ? __expf(v0 - m) : 0.f;
        float e1 = __expf(v1 - m);
        float e2 = (lane + 64 < S_) ? __expf(v2 - m) : 0.f;
        float e3 = (lane + 96 < S_) ? __expf(v3 - m) : 0.f;
        float s = e0 + e1 + e2 + e3;
#pragma unroll
        for (int off = 16; off > 0; off >>= 1)
            s += __shfl_xor_sync(0xffffffffu, s, off);
        float inv = 1.f / s;
        if (lane < S_) sc[r * SC_STR + lane] = roundtf(e0 * inv);
        sc[r * SC_STR + lane + 32] = roundtf(e1 * inv);
        if (lane + 64 < S_) sc[r * SC_STR + lane + 64] = roundtf(e2 * inv);
        if (lane + 96 < S_) sc[r * SC_STR + lane + 96] = roundtf(e3 * inv);
    }
    __syncthreads();

    if (warp < 7) {
        float acc[8][4];
#pragma unroll
        for (int ni = 0; ni < 8; ni++)
#pragma unroll
            for (int c = 0; c < 4; c++) acc[ni][c] = 0.f;
        const uint32_t* scu = (const uint32_t*)sc;
        const uint32_t* vsu = (const uint32_t*)vs;
        int m = warp * 16 + g;
#pragma unroll
        for (int ks = 0; ks < 13; ks++) {
            int k0 = ks * 8;
            uint32_t a[4];
            a[0] = scu[m * SC_STR + k0 + tg];
            a[1] = scu[(m + 8) * SC_STR + k0 + tg];
            a[2] = scu[m * SC_STR + k0 + tg + 4];
            a[3] = scu[(m + 8) * SC_STR + k0 + tg + 4];
#pragma unroll
            for (int ni = 0; ni < 8; ni++) {
                uint32_t bf[2];
                bf[0] = vsu[(k0 + tg) * VS_STR + ni * 8 + g];
                bf[1] = vsu[(k0 + tg + 4) * VS_STR + ni * 8 + g];
                mma_tf32(acc[ni], a, bf);
            }
        }
        const size_t cbase = (size_t)b * S_ * D_ + (size_t)h * DEPTH_;
#pragma unroll
        for (int ni = 0; ni < 8; ni++)
#pragma unroll
            for (int rr = 0; rr < 2; rr++) {
                int row = warp * 16 + rr * 8 + g;
                if (row < S_) {
                    int col = ni * 8 + tg * 2;
                    *(float2*)&ctx[cbase + (size_t)row * D_ + col] =
                        make_float2(roundtf(acc[ni][rr * 2]), roundtf(acc[ni][rr * 2 + 1]));
                }
            }
    }
}

// ---------------------------------------------------------------------------
// Fused split-K reduce + bias + residual + LayerNorm.
// ---------------------------------------------------------------------------
template <bool ROUND2>
__global__ __launch_bounds__(256)
void lnred_kernel(const float* __restrict__ p0, const float* __restrict__ p1,
                  const float* __restrict__ bias, const float* __restrict__ res,
                  const float* __restrict__ gamma, const float* __restrict__ beta,
                  float* __restrict__ out, float* __restrict__ out_r) {
    int row = blockIdx.x;
    size_t base = (size_t)row * D_;
    int tid = threadIdx.x;

    float vals[4];
    float sum = 0.f, sq = 0.f;
#pragma unroll
    for (int r = 0; r < 4; r++) {
        int d = tid + r * 256;
        float v = p0[base + d] + p1[base + d] + bias[d] + res[base + d];
        vals[r] = v;
        sum += v;
        sq += v * v;
    }
#pragma unroll
    for (int off = 16; off > 0; off >>= 1) {
        sum += __shfl_xor_sync(0xffffffffu, sum, off);
        sq += __shfl_xor_sync(0xffffffffu, sq, off);
    }
    __shared__ float s1[8], s2[8];
    int wid = tid >> 5, lid = tid & 31;
    if (lid == 0) { s1[wid] = sum; s2[wid] = sq; }
    __syncthreads();
    if (wid == 0) {
        sum = (lid < 8) ? s1[lid] : 0.f;
        sq = (lid < 8) ? s2[lid] : 0.f;
#pragma unroll
        for (int off = 4; off > 0; off >>= 1) {
            sum += __shfl_xor_sync(0xffffffffu, sum, off);
            sq += __shfl_xor_sync(0xffffffffu, sq, off);
        }
        if (lid == 0) { s1[0] = sum; s2[0] = sq; }
    }
    __syncthreads();
    float mean = s1[0] * (1.0f / D_);
    float var = s2[0] * (1.0f / D_) - mean * mean;
    float inv = rsqrtf(var + EPS_);
#pragma unroll
    for (int r = 0; r < 4; r++) {
        int d = tid + r * 256;
        float o = gamma[d] * ((vals[r] - mean) * inv) + beta[d];
        out[base + d] = o;
        if (ROUND2) out_r[base + d] = roundtf(o);
    }
}

// ---------------------------------------------------------------------------
// Launch
// ---------------------------------------------------------------------------
extern "C" void kernel_launch(void* const* d_in, const int* in_sizes, int n_in,
                              void* d_out, int out_size) {
    const int* tokens = (const int*)d_in[0];
    const float* emb = (const float*)d_in[1];
    const float* Wq = (const float*)d_in[2];
    const float* bq = (const float*)d_in[3];
    const float* Wk = (const float*)d_in[4];
    const float* bk = (const float*)d_in[5];
    const float* Wv = (const float*)d_in[6];
    const float* bv = (const float*)d_in[7];
    const float* Wo = (const float*)d_in[8];
    const float* bo = (const float*)d_in[9];
    const float* W1 = (const float*)d_in[10];
    const float* b1 = (const float*)d_in[11];
    const float* W2 = (const float*)d_in[12];
    const float* b2 = (const float*)d_in[13];
    const float* gamma1 = (const float*)d_in[14];
    const float* beta1 = (const float*)d_in[15];
    const float* gamma2 = (const float*)d_in[16];
    const float* beta2 = (const float*)d_in[17];
    float* out = (float*)d_out;

    float *pe, *x, *xr, *Wqkv, *bqkv, *Wor, *W1r, *W2r, *QKV, *ctx, *t1, *x1, *x1r, *ffh;
    cudaGetSymbolAddress((void**)&pe, g_pe);
    cudaGetSymbolAddress((void**)&x, g_x);
    cudaGetSymbolAddress((void**)&xr, g_xr);
    cudaGetSymbolAddress((void**)&Wqkv, g_Wqkv);
    cudaGetSymbolAddress((void**)&bqkv, g_bqkv);
    cudaGetSymbolAddress((void**)&Wor, g_Wor);
    cudaGetSymbolAddress((void**)&W1r, g_W1r);
    cudaGetSymbolAddress((void**)&W2r, g_W2r);
    cudaGetSymbolAddress((void**)&QKV, g_QKV);
    cudaGetSymbolAddress((void**)&ctx, g_ctx);
    cudaGetSymbolAddress((void**)&t1, g_t1);
    cudaGetSymbolAddress((void**)&x1, g_x1);
    cudaGetSymbolAddress((void**)&x1r, g_x1r);
    cudaGetSymbolAddress((void**)&ffh, g_ffh);

    cudaFuncSetAttribute(attention_kernel,
                         cudaFuncAttributeMaxDynamicSharedMemorySize, ATT_SMEM);
    cudaFuncSetAttribute(mma_gemm<0>,
                         cudaFuncAttributeMaxDynamicSharedMemorySize, SMEM_GEMM);
    cudaFuncSetAttribute(mma_gemm<1>,
                         cudaFuncAttributeMaxDynamicSharedMemorySize, SMEM_GEMM);
    cudaFuncSetAttribute(mma_gemm<11>,
                         cudaFuncAttributeMaxDynamicSharedMemorySize, SMEM_GEMM);

    // 1. positional encoding + embedding (+ rounded twin)
    pe_kernel<<<(S_ * D_ + 255) / 256, 256>>>(pe);
    embed_kernel<<<(BS_ * D_ / 4 + 255) / 256, 256>>>(tokens, emb, pe, x, xr);

    // 2. weight prep
    permute_qkv_kernel<<<(3 * D_ * D_ + 255) / 256, 256>>>(Wq, Wk, Wv, bq, bk, bv,
                                                           Wqkv, bqkv);
    roundcpy3_kernel<<<(N4_WO + N4_W1 + N4_W2 + 255) / 256, 256>>>(Wo, Wor, W1, W1r,
                                                                   W2, W2r);

    // 3. fused QKV projection
    mma_gemm<1><<<dim3(N_QKV / 128, BS_ / 128), 128, SMEM_GEMM>>>(
        xr, Wqkv, QKV, bqkv, nullptr, BS_, N_QKV, D_);

    // 4. attention (tensor-core QK + AV; rounds ctx)
    attention_kernel<<<B_ * H_, 256, ATT_SMEM>>>(QKV, ctx);

    // 5. output projection (split-K 2, raw partials) + fused reduce+LN1
    mma_gemm<0><<<dim3(D_ / 128, BS_ / 128, 2), 128, SMEM_GEMM>>>(
        ctx, Wor, t1, nullptr, nullptr, BS_, D_, D_);
    lnred_kernel<true><<<BS_, 256>>>(t1, t1 + (size_t)BS_ * D_, bo, x,
                                     gamma1, beta1, x1, x1r);

    // 6. FFN: W1 (bias+relu+round epilogue), W2 (split-K 2, raw partials)
    mma_gemm<11><<<dim3(F_ / 128, BS_ / 128), 128, SMEM_GEMM>>>(
        x1r, W1r, ffh, b1, nullptr, BS_, F_, D_);
    mma_gemm<0><<<dim3(D_ / 128, BS_ / 128, 2), 128, SMEM_GEMM>>>(
        ffh, W2r, t1, nullptr, nullptr, BS_, D_, F_);

    // 7. fused reduce + LN2 -> output
    lnred_kernel<false><<<BS_, 256>>>(t1, t1 + (size_t)BS_ * D_, b2, x1,
                                      gamma2, beta2, out, nullptr);
}

// round 11
// speedup vs baseline: 2.5008x; 1.4253x over previous
#include <cuda_runtime.h>
#include <cuda_fp16.h>
#include <math.h>
#include <stdint.h>

// Problem constants
#define B_ 64
#define S_ 100
#define D_ 1024
#define H_ 16
#define F_ 4096
#define DEPTH_ 64
#define BS_ (B_ * S_)          // 6400
#define N_QKV 3072
#define EPS_ 1e-6f

// ---------------------------------------------------------------------------
// Scratch (device globals; no allocations allowed)
// ---------------------------------------------------------------------------
__device__ float g_pe[S_ * D_];
__device__ float g_x[BS_ * D_];          // fp32 residual
__device__ __half g_xh[BS_ * D_];        // fp16 GEMM A operand
__device__ __half g_WqkvTh[N_QKV * D_];  // [N,K] fp16
__device__ float g_bqkv[N_QKV];
__device__ __half g_WoTh[D_ * D_];       // [N,K] fp16
__device__ __half g_W1Th[F_ * D_];       // [N,K] fp16
__device__ __half g_W2Th[D_ * F_];       // [N,K] fp16
__device__ __half g_QKVh[BS_ * N_QKV];   // fp16 QKV
__device__ __half g_ctxh[BS_ * D_];      // fp16 attention output
__device__ float g_t1[2 * BS_ * D_];     // split-K fp32 partials
__device__ float g_x1[BS_ * D_];         // fp32 residual
__device__ __half g_x1h[BS_ * D_];       // fp16 twin
__device__ __half g_ffhh[BS_ * F_];      // fp16 relu output

__device__ __forceinline__ uint32_t f2tf32(float x) {
    uint32_t r;
    asm("cvt.rna.tf32.f32 %0, %1;" : "=r"(r) : "f"(x));
    return r;
}
__device__ __forceinline__ float roundtf(float x) {
    return __uint_as_float(f2tf32(x));
}

__device__ __forceinline__ void mma_tf32(float* d, const uint32_t* a, const uint32_t* b) {
    asm volatile(
        "mma.sync.aligned.m16n8k8.row.col.f32.tf32.tf32.f32 "
        "{%0,%1,%2,%3}, {%4,%5,%6,%7}, {%8,%9}, {%0,%1,%2,%3};\n"
        : "+f"(d[0]), "+f"(d[1]), "+f"(d[2]), "+f"(d[3])
        : "r"(a[0]), "r"(a[1]), "r"(a[2]), "r"(a[3]), "r"(b[0]), "r"(b[1]));
}

__device__ __forceinline__ void mma_f16(float* d, const uint32_t* a, const uint32_t* b) {
    asm volatile(
        "mma.sync.aligned.m16n8k16.row.col.f32.f16.f16.f32 "
        "{%0,%1,%2,%3}, {%4,%5,%6,%7}, {%8,%9}, {%0,%1,%2,%3};\n"
        : "+f"(d[0]), "+f"(d[1]), "+f"(d[2]), "+f"(d[3])
        : "r"(a[0]), "r"(a[1]), "r"(a[2]), "r"(a[3]), "r"(b[0]), "r"(b[1]));
}

// ---------------------------------------------------------------------------
// Positional encoding (fp64 to match numpy float64 table)
// ---------------------------------------------------------------------------
__global__ void pe_kernel(float* __restrict__ pe) {
    int idx = blockIdx.x * blockDim.x + threadIdx.x;
    if (idx >= S_ * D_) return;
    int s = idx / D_;
    int d = idx % D_;
    int k2 = d & ~1;
    double div = pow(10000.0, (double)k2 / (double)D_);
    double arg = (double)s / div;
    pe[idx] = (float)((d & 1) ? cos(arg) : sin(arg));
}

// ---------------------------------------------------------------------------
// Embedding gather + positional add; fp32 x and fp16 xh
// ---------------------------------------------------------------------------
__global__ void embed_kernel(const int* __restrict__ tokens,
                             const float* __restrict__ emb,
                             const float* __restrict__ pe,
                             float* __restrict__ x, __half* __restrict__ xh) {
    int idx = blockIdx.x * blockDim.x + threadIdx.x;
    if (idx >= BS_ * D_ / 4) return;
    int row = idx / (D_ / 4);
    int c4 = idx % (D_ / 4);
    int tok = tokens[row];
    float4 e = ((const float4*)(emb + (size_t)tok * D_))[c4];
    float4 p = ((const float4*)(pe + (size_t)(row % S_) * D_))[c4];
    float4 o;
    o.x = e.x + p.x; o.y = e.y + p.y; o.z = e.z + p.z; o.w = e.w + p.w;
    ((float4*)x)[idx] = o;
    __half2 h0 = __floats2half2_rn(o.x, o.y);
    __half2 h1 = __floats2half2_rn(o.z, o.w);
    ((__half2*)xh)[idx * 2 + 0] = h0;
    ((__half2*)xh)[idx * 2 + 1] = h1;
}

// ---------------------------------------------------------------------------
// QKV weight transpose: W{q,k,v}[H,D,64] -> WqkvTh[3072, 1024] fp16 ([N,K])
// grid(2, 32, 48), block(32, 8)
// ---------------------------------------------------------------------------
__global__ void qkvT_kernel(const float* __restrict__ Wq, const float* __restrict__ Wk,
                            const float* __restrict__ Wv, __half* __restrict__ Wt) {
    __shared__ float t[32][33];
    int z = blockIdx.z;
    int which = z / H_, h = z % H_;
    const float* W = (which == 0) ? Wq : ((which == 1) ? Wk : Wv);
    const float* src = W + (size_t)h * D_ * DEPTH_;     // [D, 64]
    int e0 = blockIdx.x * 32, d0 = blockIdx.y * 32;
    int tx = threadIdx.x, ty = threadIdx.y;
    for (int i = ty; i < 32; i += 8)
        t[i][tx] = src[(size_t)(d0 + i) * DEPTH_ + e0 + tx];
    __syncthreads();
    __half* dst = Wt + ((size_t)which * D_ + h * DEPTH_) * D_;
    for (int i = ty; i < 32; i += 8)
        dst[(size_t)(e0 + i) * D_ + d0 + tx] = __float2half_rn(t[tx][i]);
}

__global__ void bias_concat(const float* __restrict__ bq, const float* __restrict__ bk,
                            const float* __restrict__ bv, float* __restrict__ bout) {
    int idx = blockIdx.x * blockDim.x + threadIdx.x;
    if (idx >= N_QKV) return;
    int which = idx / D_;
    int n = idx % D_;
    const float* bb = (which == 0) ? bq : ((which == 1) ? bk : bv);
    bout[idx] = bb[n];
}

// ---------------------------------------------------------------------------
// Tiled transpose + fp16 convert: src[R,C] f32 -> dst[C,R] f16. R,C % 32 == 0.
// grid(C/32, R/32), block(32, 8)
// ---------------------------------------------------------------------------
__global__ void transpose_half(const float* __restrict__ src, __half* __restrict__ dst,
                               int R, int C) {
    __shared__ float t[32][33];
    int c0 = blockIdx.x * 32, r0 = blockIdx.y * 32;
    int tx = threadIdx.x, ty = threadIdx.y;
    for (int i = ty; i < 32; i += 8)
        t[i][tx] = src[(size_t)(r0 + i) * C + c0 + tx];
    __syncthreads();
    for (int i = ty; i < 32; i += 8)
        dst[(size_t)(c0 + i) * R + r0 + tx] = __float2half_rn(t[tx][i]);
}

// ---------------------------------------------------------------------------
// FP16 mma.sync GEMM: C = A[M,K] @ Bt[N,K]^T. fp32 accumulate.
// 128x128 CTA tile, 4 warps of 64x64, k-step 32, 2-stage cp.async.
// Both smem tiles [128 rows][32 halves], u32 row stride 20 (conflict-free).
// Split-K via gridDim.z (fp32 raw partial to Cf + z*M*N; EPI must be 0).
// EPI: bit0 bias, bit1 relu, bit2 residual(fp32), bit3 fp16 output.
// ---------------------------------------------------------------------------
#define STRH 20                           // u32 per tile row (16 data + 4 pad)
#define TILEU (128 * STRH)                // 2560 u32 per operand tile
#define STAGEU (2 * TILEU)                // 5120 u32
#define SMEM_GEMM (2 * STAGEU * 4)        // 40960 B -> 3+ CTAs/SM

template <int EPI>
__global__ __launch_bounds__(128, 3)
void mma_gemm_h(const __half* __restrict__ A, const __half* __restrict__ Bt,
                void* __restrict__ Cv, const float* __restrict__ bias,
                const float* __restrict__ res, int M, int N, int K) {
    extern __shared__ uint32_t smu[];
    int tid = threadIdx.x;
    int lane = tid & 31, warp = tid >> 5;
    int wm = warp & 1, wn = warp >> 1;
    int g = lane >> 2, tg = lane & 3;
    int bm = blockIdx.y * 128, bn = blockIdx.x * 128;

    // Split-K offsets (both operands K-major, offsets in halves)
    int kspl = K / gridDim.z;
    int kOff = blockIdx.z * kspl;
    A += kOff;
    Bt += kOff;
    float* Cf = (float*)Cv + (size_t)blockIdx.z * M * N;
    __half* Ch = (__half*)Cv;

    uint32_t smemBase = (uint32_t)__cvta_generic_to_shared(smu);

    float acc[4][8][4];
#pragma unroll
    for (int i = 0; i < 4; i++)
#pragma unroll
        for (int j = 0; j < 8; j++)
#pragma unroll
            for (int c = 0; c < 4; c++) acc[i][j][c] = 0.f;

    const int KT = kspl / 32;

    // Prefetch: each tile 128 rows x 64 B (4 x 16B chunks per row).
    // thread: row = tid>>2 (+q*32), chunk = tid&3.
    int pr = tid >> 2, pc = tid & 3;
    const __half* aSrc = A + (size_t)(bm + pr) * K + pc * 8;
    const __half* bSrc = Bt + (size_t)(bn + pr) * K + pc * 8;
    uint32_t aDst0 = smemBase + (uint32_t)(pr * 80 + pc * 16);
    uint32_t bDst0 = smemBase + TILEU * 4 + (uint32_t)(pr * 80 + pc * 16);

    auto prefetch = [&](int stage) {
        uint32_t so = (uint32_t)(stage * STAGEU * 4);
#pragma unroll
        for (int q = 0; q < 4; q++) {
            uint32_t dst = aDst0 + so + (uint32_t)(q * 32 * 80);
            const __half* src = aSrc + (size_t)(q * 32) * K;
            asm volatile("cp.async.cg.shared.global [%0], [%1], 16;" :: "r"(dst), "l"(src));
        }
#pragma unroll
        for (int q = 0; q < 4; q++) {
            uint32_t dst = bDst0 + so + (uint32_t)(q * 32 * 80);
            const __half* src = bSrc + (size_t)(q * 32) * K;
            asm volatile("cp.async.cg.shared.global [%0], [%1], 16;" :: "r"(dst), "l"(src));
        }
        aSrc += 32;
        bSrc += 32;
    };

    prefetch(0);
    asm volatile("cp.async.commit_group;");

    for (int kt = 0; kt < KT; kt++) {
        if (kt + 1 < KT) prefetch((kt + 1) & 1);
        asm volatile("cp.async.commit_group;");
        asm volatile("cp.async.wait_group 1;");
        __syncthreads();

        const uint32_t* As = smu + (kt & 1) * STAGEU;
        const uint32_t* Bs = As + TILEU;
#pragma unroll
        for (int ks = 0; ks < 2; ks++) {
            int ku = ks * 8;   // u32 col base for this k16 slice
            uint32_t afr[4][4];
#pragma unroll
            for (int mi = 0; mi < 4; mi++) {
                int m = wm * 64 + mi * 16 + g;
                afr[mi][0] = As[m * STRH + ku + tg];
                afr[mi][1] = As[(m + 8) * STRH + ku + tg];
                afr[mi][2] = As[m * STRH + ku + tg + 4];
                afr[mi][3] = As[(m + 8) * STRH + ku + tg + 4];
            }
            uint32_t bfr[8][2];
#pragma unroll
            for (int ni = 0; ni < 8; ni++) {
                int n = wn * 64 + ni * 8 + g;
                bfr[ni][0] = Bs[n * STRH + ku + tg];
                bfr[ni][1] = Bs[n * STRH + ku + tg + 4];
            }
#pragma unroll
            for (int mi = 0; mi < 4; mi++)
#pragma unroll
                for (int ni = 0; ni < 8; ni++)
                    mma_f16(acc[mi][ni], afr[mi], bfr[ni]);
        }
        __syncthreads();
    }

#pragma unroll
    for (int mi = 0; mi < 4; mi++) {
#pragma unroll
        for (int rr = 0; rr < 2; rr++) {
            int row = bm + wm * 64 + mi * 16 + rr * 8 + g;
#pragma unroll
            for (int ni = 0; ni < 8; ni++) {
                int col = bn + wn * 64 + ni * 8 + tg * 2;
                float vx = acc[mi][ni][rr * 2 + 0];
                float vy = acc[mi][ni][rr * 2 + 1];
                if (EPI & 1) { vx += bias[col]; vy += bias[col + 1]; }
                if (EPI & 4) {
                    const float* rp = res + (size_t)row * N + col;
                    vx += rp[0]; vy += rp[1];
                }
                if (EPI & 2) { vx = fmaxf(vx, 0.f); vy = fmaxf(vy, 0.f); }
                if (EPI & 8) {
                    *(__half2*)&Ch[(size_t)row * N + col] = __floats2half2_rn(vx, vy);
                } else {
                    *(float2*)&Cf[(size_t)row * N + col] = make_float2(vx, vy);
                }
            }
        }
    }
}

// ---------------------------------------------------------------------------
// Fused attention per (b, h) — tensor-core QK^T and AV via mma.sync tf32.
// Reads fp16 QKV (exactly representable in tf32); writes fp16 ctx.
// ---------------------------------------------------------------------------
#define QS_STR 76
#define KT_STR 104
#define VS_STR 72
#define SC_STR 108
#define QROWS 112
#define VROWS 104
#define SROWS 112
#define ATT_FLOATS (QROWS * QS_STR + DEPTH_ * KT_STR + VROWS * VS_STR + SROWS * SC_STR)
#define ATT_SMEM (ATT_FLOATS * 4)

__global__ __launch_bounds__(256)
void attention_kernel(const __half* __restrict__ QKV, __half* __restrict__ ctx) {
    extern __shared__ float sm[];
    float* qs = sm;
    float* kt = qs + QROWS * QS_STR;
    float* vs = kt + DEPTH_ * KT_STR;
    float* sc = vs + VROWS * VS_STR;

    int bh = blockIdx.x;
    int b = bh / H_;
    int h = bh % H_;
    int tid = threadIdx.x;
    int lane = tid & 31, warp = tid >> 5;
    int g = lane >> 2, tg = lane & 3;

    for (int i = tid; i < ATT_FLOATS; i += 256) sm[i] = 0.f;
    __syncthreads();

    for (int i = tid; i < S_ * (DEPTH_ / 4); i += 256) {
        int s = i >> 4, e4 = (i & 15) * 4;
        size_t off = ((size_t)(b * S_ + s)) * N_QKV + h * DEPTH_ + e4;
        float2 q01 = __half22float2(*(const __half2*)(QKV + off));
        float2 q23 = __half22float2(*(const __half2*)(QKV + off + 2));
        float2 k01 = __half22float2(*(const __half2*)(QKV + off + D_));
        float2 k23 = __half22float2(*(const __half2*)(QKV + off + D_ + 2));
        float2 v01 = __half22float2(*(const __half2*)(QKV + off + 2 * D_));
        float2 v23 = __half22float2(*(const __half2*)(QKV + off + 2 * D_ + 2));
        qs[s * QS_STR + e4 + 0] = q01.x; qs[s * QS_STR + e4 + 1] = q01.y;
        qs[s * QS_STR + e4 + 2] = q23.x; qs[s * QS_STR + e4 + 3] = q23.y;
        kt[(e4 + 0) * KT_STR + s] = k01.x; kt[(e4 + 1) * KT_STR + s] = k01.y;
        kt[(e4 + 2) * KT_STR + s] = k23.x; kt[(e4 + 3) * KT_STR + s] = k23.y;
        *(float4*)&vs[s * VS_STR + e4] = make_float4(v01.x, v01.y, v23.x, v23.y);
    }
    __syncthreads();

    if (warp < 7) {
        float acc[13][4];
#pragma unroll
        for (int ni = 0; ni < 13; ni++)
#pragma unroll
            for (int c = 0; c < 4; c++) acc[ni][c] = 0.f;
        const uint32_t* qsu = (const uint32_t*)qs;
        const uint32_t* ktu = (const uint32_t*)kt;
        int m = warp * 16 + g;
#pragma unroll
        for (int ks = 0; ks < 8; ks++) {
            int k0 = ks * 8;
            uint32_t a[4];
            a[0] = qsu[m * QS_STR + k0 + tg];
            a[1] = qsu[(m + 8) * QS_STR + k0 + tg];
            a[2] = qsu[m * QS_STR + k0 + tg + 4];
            a[3] = qsu[(m + 8) * QS_STR + k0 + tg + 4];
#pragma unroll
            for (int ni = 0; ni < 13; ni++) {
                uint32_t bf[2];
                bf[0] = ktu[(k0 + tg) * KT_STR + ni * 8 + g];
                bf[1] = ktu[(k0 + tg + 4) * KT_STR + ni * 8 + g];
                mma_tf32(acc[ni], a, bf);
            }
        }
        const float scale = 0.125f;
#pragma unroll
        for (int ni = 0; ni < 13; ni++)
#pragma unroll
            for (int rr = 0; rr < 2; rr++) {
                int row = warp * 16 + rr * 8 + g;
                int col = ni * 8 + tg * 2;
                *(float2*)&sc[row * SC_STR + col] =
                    make_float2(acc[ni][rr * 2] * scale, acc[ni][rr * 2 + 1] * scale);
            }
    }
    __syncthreads();

    for (int r = warp; r < S_; r += 8) {
        float v0 = (lane < S_) ? sc[r * SC_STR + lane] : -1e30f;
        float v1 = sc[r * SC_STR + lane + 32];
        float v2 = (lane + 64 < S_) ? sc[r * SC_STR + lane + 64] : -1e30f;
        float v3 = (lane + 96 < S_) ? sc[r * SC_STR + lane + 96] : -1e30f;
        float m = fmaxf(fmaxf(v0, v1), fmaxf(v2, v3));
#pragma unroll
        for (int off = 16; off > 0; off >>= 1)
            m = fmaxf(m, __shfl_xor_sync(0xffffffffu, m, off));
        float e0 = (lane < S_) ? __expf(v0 - m) : 0.f;
        float e1 = __expf(v1 - m);
        float e2 = (lane + 64 < S_) ? __expf(v2 - m) : 0.f;
        float e3 = (lane + 96 < S_) ? __expf(v3 - m) : 0.f;
        float s = e0 + e1 + e2 + e3;
#pragma unroll
        for (int off = 16; off > 0; off >>= 1)
            s += __shfl_xor_sync(0xffffffffu, s, off);
        float inv = 1.f / s;
        if (lane < S_) sc[r * SC_STR + lane] = roundtf(e0 * inv);
        sc[r * SC_STR + lane + 32] = roundtf(e1 * inv);
        if (lane + 64 < S_) sc[r * SC_STR + lane + 64] = roundtf(e2 * inv);
        if (lane + 96 < S_) sc[r * SC_STR + lane + 96] = roundtf(e3 * inv);
    }
    __syncthreads();

    if (warp < 7) {
        float acc[8][4];
#pragma unroll
        for (int ni = 0; ni < 8; ni++)
#pragma unroll
            for (int c = 0; c < 4; c++) acc[ni][c] = 0.f;
        const uint32_t* scu = (const uint32_t*)sc;
        const uint32_t* vsu = (const uint32_t*)vs;
        int m = warp * 16 + g;
#pragma unroll
        for (int ks = 0; ks < 13; ks++) {
            int k0 = ks * 8;
            uint32_t a[4];
            a[0] = scu[m * SC_STR + k0 + tg];
            a[1] = scu[(m + 8) * SC_STR + k0 + tg];
            a[2] = scu[m * SC_STR + k0 + tg + 4];
            a[3] = scu[(m + 8) * SC_STR + k0 + tg + 4];
#pragma unroll
            for (int ni = 0; ni < 8; ni++) {
                uint32_t bf[2];
                bf[0] = vsu[(k0 + tg) * VS_STR + ni * 8 + g];
                bf[1] = vsu[(k0 + tg + 4) * VS_STR + ni * 8 + g];
                mma_tf32(acc[ni], a, bf);
            }
        }
        const size_t cbase = (size_t)b * S_ * D_ + (size_t)h * DEPTH_;
#pragma unroll
        for (int ni = 0; ni < 8; ni++)
#pragma unroll
            for (int rr = 0; rr < 2; rr++) {
                int row = warp * 16 + rr * 8 + g;
                if (row < S_) {
                    int col = ni * 8 + tg * 2;
                    *(__half2*)&ctx[cbase + (size_t)row * D_ + col] =
                        __floats2half2_rn(acc[ni][rr * 2], acc[ni][rr * 2 + 1]);
                }
            }
    }
}

// ---------------------------------------------------------------------------
// Fused split-K reduce + bias + residual + LayerNorm.
// Writes fp32 out; optional fp16 twin.
// ---------------------------------------------------------------------------
template <bool HALF2>
__global__ __launch_bounds__(256)
void lnred_kernel(const float* __restrict__ p0, const float* __restrict__ p1,
                  const float* __restrict__ bias, const float* __restrict__ res,
                  const float* __restrict__ gamma, const float* __restrict__ beta,
                  float* __restrict__ out, __half* __restrict__ out_h) {
    int row = blockIdx.x;
    size_t base = (size_t)row * D_;
    int tid = threadIdx.x;

    float vals[4];
    float sum = 0.f, sq = 0.f;
#pragma unroll
    for (int r = 0; r < 4; r++) {
        int d = tid + r * 256;
        float v = p0[base + d] + p1[base + d] + bias[d] + res[base + d];
        vals[r] = v;
        sum += v;
        sq += v * v;
    }
#pragma unroll
    for (int off = 16; off > 0; off >>= 1) {
        sum += __shfl_xor_sync(0xffffffffu, sum, off);
        sq += __shfl_xor_sync(0xffffffffu, sq, off);
    }
    __shared__ float s1[8], s2[8];
    int wid = tid >> 5, lid = tid & 31;
    if (lid == 0) { s1[wid] = sum; s2[wid] = sq; }
    __syncthreads();
    if (wid == 0) {
        sum = (lid < 8) ? s1[lid] : 0.f;
        sq = (lid < 8) ? s2[lid] : 0.f;
#pragma unroll
        for (int off = 4; off > 0; off >>= 1) {
            sum += __shfl_xor_sync(0xffffffffu, sum, off);
            sq += __shfl_xor_sync(0xffffffffu, sq, off);
        }
        if (lid == 0) { s1[0] = sum; s2[0] = sq; }
    }
    __syncthreads();
    float mean = s1[0] * (1.0f / D_);
    float var = s2[0] * (1.0f / D_) - mean * mean;
    float inv = rsqrtf(var + EPS_);
#pragma unroll
    for (int r = 0; r < 4; r++) {
        int d = tid + r * 256;
        float o = gamma[d] * ((vals[r] - mean) * inv) + beta[d];
        out[base + d] = o;
        if (HALF2) out_h[base + d] = __float2half_rn(o);
    }
}

// ---------------------------------------------------------------------------
// Launch
// ---------------------------------------------------------------------------
extern "C" void kernel_launch(void* const* d_in, const int* in_sizes, int n_in,
                              void* d_out, int out_size) {
    const int* tokens = (const int*)d_in[0];
    const float* emb = (const float*)d_in[1];
    const float* Wq = (const float*)d_in[2];
    const float* bq = (const float*)d_in[3];
    const float* Wk = (const float*)d_in[4];
    const float* bk = (const float*)d_in[5];
    const float* Wv = (const float*)d_in[6];
    const float* bv = (const float*)d_in[7];
    const float* Wo = (const float*)d_in[8];
    const float* bo = (const float*)d_in[9];
    const float* W1 = (const float*)d_in[10];
    const float* b1 = (const float*)d_in[11];
    const float* W2 = (const float*)d_in[12];
    const float* b2 = (const float*)d_in[13];
    const float* gamma1 = (const float*)d_in[14];
    const float* beta1 = (const float*)d_in[15];
    const float* gamma2 = (const float*)d_in[16];
    const float* beta2 = (const float*)d_in[17];
    float* out = (float*)d_out;

    float *pe, *x, *bqkv, *t1, *x1;
    __half *xh, *WqkvTh, *WoTh, *W1Th, *W2Th, *QKVh, *ctxh, *x1h, *ffhh;
    cudaGetSymbolAddress((void**)&pe, g_pe);
    cudaGetSymbolAddress((void**)&x, g_x);
    cudaGetSymbolAddress((void**)&xh, g_xh);
    cudaGetSymbolAddress((void**)&WqkvTh, g_WqkvTh);
    cudaGetSymbolAddress((void**)&bqkv, g_bqkv);
    cudaGetSymbolAddress((void**)&WoTh, g_WoTh);
    cudaGetSymbolAddress((void**)&W1Th, g_W1Th);
    cudaGetSymbolAddress((void**)&W2Th, g_W2Th);
    cudaGetSymbolAddress((void**)&QKVh, g_QKVh);
    cudaGetSymbolAddress((void**)&ctxh, g_ctxh);
    cudaGetSymbolAddress((void**)&t1, g_t1);
    cudaGetSymbolAddress((void**)&x1, g_x1);
    cudaGetSymbolAddress((void**)&x1h, g_x1h);
    cudaGetSymbolAddress((void**)&ffhh, g_ffhh);

    cudaFuncSetAttribute(attention_kernel,
                         cudaFuncAttributeMaxDynamicSharedMemorySize, ATT_SMEM);
    cudaFuncSetAttribute(mma_gemm_h<0>,
                         cudaFuncAttributeMaxDynamicSharedMemorySize, SMEM_GEMM);
    cudaFuncSetAttribute(mma_gemm_h<9>,
                         cudaFuncAttributeMaxDynamicSharedMemorySize, SMEM_GEMM);
    cudaFuncSetAttribute(mma_gemm_h<11>,
                         cudaFuncAttributeMaxDynamicSharedMemorySize, SMEM_GEMM);

    // 1. positional encoding + embedding (fp32 + fp16 twin)
    pe_kernel<<<(S_ * D_ + 255) / 256, 256>>>(pe);
    embed_kernel<<<(BS_ * D_ / 4 + 255) / 256, 256>>>(tokens, emb, pe, x, xh);

    // 2. weight prep: transpose to [N,K] fp16
    qkvT_kernel<<<dim3(2, 32, 48), dim3(32, 8)>>>(Wq, Wk, Wv, WqkvTh);
    bias_concat<<<(N_QKV + 255) / 256, 256>>>(bq, bk, bv, bqkv);
    transpose_half<<<dim3(32, 32), dim3(32, 8)>>>(Wo, WoTh, D_, D_);
    transpose_half<<<dim3(128, 32), dim3(32, 8)>>>(W1, W1Th, D_, F_);
    transpose_half<<<dim3(32, 128), dim3(32, 8)>>>(W2, W2Th, F_, D_);

    // 3. fused QKV projection (bias + fp16 output)
    mma_gemm_h<9><<<dim3(N_QKV / 128, BS_ / 128), 128, SMEM_GEMM>>>(
        xh, WqkvTh, QKVh, bqkv, nullptr, BS_, N_QKV, D_);

    // 4. attention (tensor-core QK + AV; fp16 in/out)
    attention_kernel<<<B_ * H_, 256, ATT_SMEM>>>(QKVh, ctxh);

    // 5. output projection (split-K 2, fp32 partials) + fused reduce+LN1
    mma_gemm_h<0><<<dim3(D_ / 128, BS_ / 128, 2), 128, SMEM_GEMM>>>(
        ctxh, WoTh, t1, nullptr, nullptr, BS_, D_, D_);
    lnred_kernel<true><<<BS_, 256>>>(t1, t1 + (size_t)BS_ * D_, bo, x,
                                     gamma1, beta1, x1, x1h);

    // 6. FFN: W1 (bias+relu+fp16 out), W2 (split-K 2, fp32 partials)
    mma_gemm_h<11><<<dim3(F_ / 128, BS_ / 128), 128, SMEM_GEMM>>>(
        x1h, W1Th, ffhh, b1, nullptr, BS_, F_, D_);
    mma_gemm_h<0><<<dim3(D_ / 128, BS_ / 128, 2), 128, SMEM_GEMM>>>(
        ffhh, W2Th, t1, nullptr, nullptr, BS_, D_, F_);

    // 7. fused reduce + LN2 -> output
    lnred_kernel<false><<<BS_, 256>>>(t1, t1 + (size_t)BS_ * D_, b2, x1,
                                      gamma2, beta2, out, nullptr);
}

// round 12
// speedup vs baseline: 2.5446x; 1.0175x over previous
#include <cuda_runtime.h>
#include <cuda_fp16.h>
#include <math.h>
#include <stdint.h>

// Problem constants
#define B_ 64
#define S_ 100
#define D_ 1024
#define H_ 16
#define F_ 4096
#define DEPTH_ 64
#define BS_ (B_ * S_)          // 6400
#define N_QKV 3072
#define EPS_ 1e-6f

// ---------------------------------------------------------------------------
// Scratch (device globals; no allocations allowed)
// ---------------------------------------------------------------------------
__device__ float g_pe[S_ * D_];
__device__ float g_x[BS_ * D_];          // fp32 residual
__device__ __half g_xh[BS_ * D_];        // fp16 GEMM A operand
__device__ __half g_WqkvTh[N_QKV * D_];  // [N,K] fp16
__device__ float g_bqkv[N_QKV];
__device__ __half g_WoTh[D_ * D_];       // [N,K] fp16
__device__ __half g_W1Th[F_ * D_];       // [N,K] fp16
__device__ __half g_W2Th[D_ * F_];       // [N,K] fp16
__device__ __half g_QKVh[BS_ * N_QKV];   // fp16 QKV
__device__ __half g_ctxh[BS_ * D_];      // fp16 attention output
__device__ float g_t1[2 * BS_ * D_];     // split-K fp32 partials
__device__ float g_x1[BS_ * D_];         // fp32 residual
__device__ __half g_x1h[BS_ * D_];       // fp16 twin
__device__ __half g_ffhh[BS_ * F_];      // fp16 relu output

__device__ __forceinline__ void mma_f16(float* d, const uint32_t* a, const uint32_t* b) {
    asm volatile(
        "mma.sync.aligned.m16n8k16.row.col.f32.f16.f16.f32 "
        "{%0,%1,%2,%3}, {%4,%5,%6,%7}, {%8,%9}, {%0,%1,%2,%3};\n"
        : "+f"(d[0]), "+f"(d[1]), "+f"(d[2]), "+f"(d[3])
        : "r"(a[0]), "r"(a[1]), "r"(a[2]), "r"(a[3]), "r"(b[0]), "r"(b[1]));
}

// ---------------------------------------------------------------------------
// Positional encoding (fp64 to match numpy float64 table)
// ---------------------------------------------------------------------------
__global__ void pe_kernel(float* __restrict__ pe) {
    int idx = blockIdx.x * blockDim.x + threadIdx.x;
    if (idx >= S_ * D_) return;
    int s = idx / D_;
    int d = idx % D_;
    int k2 = d & ~1;
    double div = pow(10000.0, (double)k2 / (double)D_);
    double arg = (double)s / div;
    pe[idx] = (float)((d & 1) ? cos(arg) : sin(arg));
}

// ---------------------------------------------------------------------------
// Embedding gather + positional add; fp32 x, fp16 xh. Also concats QKV bias.
// ---------------------------------------------------------------------------
__global__ void embed_kernel(const int* __restrict__ tokens,
                             const float* __restrict__ emb,
                             const float* __restrict__ pe,
                             float* __restrict__ x, __half* __restrict__ xh,
                             const float* __restrict__ bq, const float* __restrict__ bk,
                             const float* __restrict__ bv, float* __restrict__ bqkv) {
    int idx = blockIdx.x * blockDim.x + threadIdx.x;
    if (idx < N_QKV) {
        int which = idx / D_;
        int n = idx % D_;
        const float* bb = (which == 0) ? bq : ((which == 1) ? bk : bv);
        bqkv[idx] = bb[n];
    }
    if (idx >= BS_ * D_ / 4) return;
    int row = idx / (D_ / 4);
    int c4 = idx % (D_ / 4);
    int tok = tokens[row];
    float4 e = ((const float4*)(emb + (size_t)tok * D_))[c4];
    float4 p = ((const float4*)(pe + (size_t)(row % S_) * D_))[c4];
    float4 o;
    o.x = e.x + p.x; o.y = e.y + p.y; o.z = e.z + p.z; o.w = e.w + p.w;
    ((float4*)x)[idx] = o;
    ((__half2*)xh)[idx * 2 + 0] = __floats2half2_rn(o.x, o.y);
    ((__half2*)xh)[idx * 2 + 1] = __floats2half2_rn(o.z, o.w);
}

// ---------------------------------------------------------------------------
// QKV weight transpose: W{q,k,v}[H,D,64] -> WqkvTh[3072, 1024] fp16 ([N,K])
// grid(2, 32, 48), block(32, 8)
// ---------------------------------------------------------------------------
__global__ void qkvT_kernel(const float* __restrict__ Wq, const float* __restrict__ Wk,
                            const float* __restrict__ Wv, __half* __restrict__ Wt) {
    __shared__ float t[32][33];
    int z = blockIdx.z;
    int which = z / H_, h = z % H_;
    const float* W = (which == 0) ? Wq : ((which == 1) ? Wk : Wv);
    const float* src = W + (size_t)h * D_ * DEPTH_;
    int e0 = blockIdx.x * 32, d0 = blockIdx.y * 32;
    int tx = threadIdx.x, ty = threadIdx.y;
    for (int i = ty; i < 32; i += 8)
        t[i][tx] = src[(size_t)(d0 + i) * DEPTH_ + e0 + tx];
    __syncthreads();
    __half* dst = Wt + ((size_t)which * D_ + h * DEPTH_) * D_;
    for (int i = ty; i < 32; i += 8)
        dst[(size_t)(e0 + i) * D_ + d0 + tx] = __float2half_rn(t[tx][i]);
}

// ---------------------------------------------------------------------------
// Tiled transpose + fp16 convert: src[R,C] f32 -> dst[C,R] f16.
// ---------------------------------------------------------------------------
__global__ void transpose_half(const float* __restrict__ src, __half* __restrict__ dst,
                               int R, int C) {
    __shared__ float t[32][33];
    int c0 = blockIdx.x * 32, r0 = blockIdx.y * 32;
    int tx = threadIdx.x, ty = threadIdx.y;
    for (int i = ty; i < 32; i += 8)
        t[i][tx] = src[(size_t)(r0 + i) * C + c0 + tx];
    __syncthreads();
    for (int i = ty; i < 32; i += 8)
        dst[(size_t)(c0 + i) * R + r0 + tx] = __float2half_rn(t[tx][i]);
}

// ---------------------------------------------------------------------------
// FP16 mma.sync GEMM (unchanged from R11 best).
// ---------------------------------------------------------------------------
#define STRH 20
#define TILEU (128 * STRH)
#define STAGEU (2 * TILEU)
#define SMEM_GEMM (2 * STAGEU * 4)

template <int EPI>
__global__ __launch_bounds__(128, 3)
void mma_gemm_h(const __half* __restrict__ A, const __half* __restrict__ Bt,
                void* __restrict__ Cv, const float* __restrict__ bias,
                const float* __restrict__ res, int M, int N, int K) {
    extern __shared__ uint32_t smu[];
    int tid = threadIdx.x;
    int lane = tid & 31, warp = tid >> 5;
    int wm = warp & 1, wn = warp >> 1;
    int g = lane >> 2, tg = lane & 3;
    int bm = blockIdx.y * 128, bn = blockIdx.x * 128;

    int kspl = K / gridDim.z;
    int kOff = blockIdx.z * kspl;
    A += kOff;
    Bt += kOff;
    float* Cf = (float*)Cv + (size_t)blockIdx.z * M * N;
    __half* Ch = (__half*)Cv;

    float acc[4][8][4];
#pragma unroll
    for (int i = 0; i < 4; i++)
#pragma unroll
        for (int j = 0; j < 8; j++)
#pragma unroll
            for (int c = 0; c < 4; c++) acc[i][j][c] = 0.f;

    const int KT = kspl / 32;

    int pr = tid >> 2, pc = tid & 3;
    const __half* aSrc = A + (size_t)(bm + pr) * K + pc * 8;
    const __half* bSrc = Bt + (size_t)(bn + pr) * K + pc * 8;
    uint32_t smemBase = (uint32_t)__cvta_generic_to_shared(smu);
    uint32_t aDst0 = smemBase + (uint32_t)(pr * 80 + pc * 16);
    uint32_t bDst0 = smemBase + TILEU * 4 + (uint32_t)(pr * 80 + pc * 16);

    auto prefetch = [&](int stage) {
        uint32_t so = (uint32_t)(stage * STAGEU * 4);
#pragma unroll
        for (int q = 0; q < 4; q++) {
            uint32_t dst = aDst0 + so + (uint32_t)(q * 32 * 80);
            const __half* src = aSrc + (size_t)(q * 32) * K;
            asm volatile("cp.async.cg.shared.global [%0], [%1], 16;" :: "r"(dst), "l"(src));
        }
#pragma unroll
        for (int q = 0; q < 4; q++) {
            uint32_t dst = bDst0 + so + (uint32_t)(q * 32 * 80);
            const __half* src = bSrc + (size_t)(q * 32) * K;
            asm volatile("cp.async.cg.shared.global [%0], [%1], 16;" :: "r"(dst), "l"(src));
        }
        aSrc += 32;
        bSrc += 32;
    };

    prefetch(0);
    asm volatile("cp.async.commit_group;");

    for (int kt = 0; kt < KT; kt++) {
        if (kt + 1 < KT) prefetch((kt + 1) & 1);
        asm volatile("cp.async.commit_group;");
        asm volatile("cp.async.wait_group 1;");
        __syncthreads();

        const uint32_t* As = smu + (kt & 1) * STAGEU;
        const uint32_t* Bs = As + TILEU;
#pragma unroll
        for (int ks = 0; ks < 2; ks++) {
            int ku = ks * 8;
            uint32_t afr[4][4];
#pragma unroll
            for (int mi = 0; mi < 4; mi++) {
                int m = wm * 64 + mi * 16 + g;
                afr[mi][0] = As[m * STRH + ku + tg];
                afr[mi][1] = As[(m + 8) * STRH + ku + tg];
                afr[mi][2] = As[m * STRH + ku + tg + 4];
                afr[mi][3] = As[(m + 8) * STRH + ku + tg + 4];
            }
            uint32_t bfr[8][2];
#pragma unroll
            for (int ni = 0; ni < 8; ni++) {
                int n = wn * 64 + ni * 8 + g;
                bfr[ni][0] = Bs[n * STRH + ku + tg];
                bfr[ni][1] = Bs[n * STRH + ku + tg + 4];
            }
#pragma unroll
            for (int mi = 0; mi < 4; mi++)
#pragma unroll
                for (int ni = 0; ni < 8; ni++)
                    mma_f16(acc[mi][ni], afr[mi], bfr[ni]);
        }
        __syncthreads();
    }

#pragma unroll
    for (int mi = 0; mi < 4; mi++) {
#pragma unroll
        for (int rr = 0; rr < 2; rr++) {
            int row = bm + wm * 64 + mi * 16 + rr * 8 + g;
#pragma unroll
            for (int ni = 0; ni < 8; ni++) {
                int col = bn + wn * 64 + ni * 8 + tg * 2;
                float vx = acc[mi][ni][rr * 2 + 0];
                float vy = acc[mi][ni][rr * 2 + 1];
                if (EPI & 1) { vx += bias[col]; vy += bias[col + 1]; }
                if (EPI & 4) {
                    const float* rp = res + (size_t)row * N + col;
                    vx += rp[0]; vy += rp[1];
                }
                if (EPI & 2) { vx = fmaxf(vx, 0.f); vy = fmaxf(vy, 0.f); }
                if (EPI & 8) {
                    *(__half2*)&Ch[(size_t)row * N + col] = __floats2half2_rn(vx, vy);
                } else {
                    *(float2*)&Cf[(size_t)row * N + col] = make_float2(vx, vy);
                }
            }
        }
    }
}

// ---------------------------------------------------------------------------
// Fused attention per (b, h) — fp16 m16n8k16 MMA for QK^T and AV.
// Smem (u32 units):
//   qh [112 rows][36 u32]  (64 halves + pad)
//   kh [112 rows][36 u32]  (K as [s][e] = natural B operand [n][k])
//   vt [64 rows][60 u32]   (V^T: [e][s], 104+ halves padded to 120)
//   ph [112 rows][60 u32]  (P fp16, K padded to 112 halves)
//   sc [112 rows][108 f32] (scores fp32 for softmax)
// Bank checks: stride 36 -> banks 4g+tg (all 32); stride 60 -> 28g+tg (all 32).
// ---------------------------------------------------------------------------
#define QH_STR 36
#define KH_STR 36
#define VT_STR 60
#define PH_STR 60
#define SCF_STR 108
#define QH_OFF 0
#define KH_OFF (QH_OFF + 112 * QH_STR)
#define VT_OFF (KH_OFF + 112 * KH_STR)
#define PH_OFF (VT_OFF + 64 * VT_STR)
#define SC_OFF (PH_OFF + 112 * PH_STR)
#define ATT_U32 (SC_OFF + 112 * SCF_STR)
#define ATT_SMEM (ATT_U32 * 4)   // 122880 bytes

__global__ __launch_bounds__(256)
void attention_kernel(const __half* __restrict__ QKV, __half* __restrict__ ctx) {
    extern __shared__ uint32_t su[];
    uint32_t* qh = su + QH_OFF;
    uint32_t* kh = su + KH_OFF;
    uint32_t* vt = su + VT_OFF;
    uint32_t* ph = su + PH_OFF;
    float* sc = (float*)(su + SC_OFF);
    __half* vth = (__half*)vt;
    __half* phh = (__half*)ph;

    int bh = blockIdx.x;
    int b = bh / H_;
    int h = bh % H_;
    int tid = threadIdx.x;
    int lane = tid & 31, warp = tid >> 5;
    int g = lane >> 2, tg = lane & 3;

    for (int i = tid; i < ATT_U32; i += 256) su[i] = 0;
    __syncthreads();

    // Load q, k (direct u32 copies) and v (transposed, scalar half stores).
    for (int i = tid; i < S_ * 16; i += 256) {
        int s = i >> 4, e4 = (i & 15) * 4;
        size_t off = ((size_t)(b * S_ + s)) * N_QKV + h * DEPTH_ + e4;
        uint32_t q0 = *(const uint32_t*)(QKV + off);
        uint32_t q1 = *(const uint32_t*)(QKV + off + 2);
        uint32_t k0 = *(const uint32_t*)(QKV + off + D_);
        uint32_t k1 = *(const uint32_t*)(QKV + off + D_ + 2);
        qh[s * QH_STR + e4 / 2] = q0;
        qh[s * QH_STR + e4 / 2 + 1] = q1;
        kh[s * KH_STR + e4 / 2] = k0;
        kh[s * KH_STR + e4 / 2 + 1] = k1;
        __half2 v01 = *(const __half2*)(QKV + off + 2 * D_);
        __half2 v23 = *(const __half2*)(QKV + off + 2 * D_ + 2);
        vth[(e4 + 0) * (VT_STR * 2) + s] = __low2half(v01);
        vth[(e4 + 1) * (VT_STR * 2) + s] = __high2half(v01);
        vth[(e4 + 2) * (VT_STR * 2) + s] = __low2half(v23);
        vth[(e4 + 3) * (VT_STR * 2) + s] = __high2half(v23);
    }
    __syncthreads();

    // --- QK^T: warps 0..6, m-tile per warp; 13 n-tiles; K=64 -> 4 k16 slices.
    if (warp < 7) {
        float acc[13][4];
#pragma unroll
        for (int ni = 0; ni < 13; ni++)
#pragma unroll
            for (int c = 0; c < 4; c++) acc[ni][c] = 0.f;
        int m = warp * 16 + g;
#pragma unroll
        for (int ks = 0; ks < 4; ks++) {
            int ku = ks * 8;
            uint32_t a[4];
            a[0] = qh[m * QH_STR + ku + tg];
            a[1] = qh[(m + 8) * QH_STR + ku + tg];
            a[2] = qh[m * QH_STR + ku + tg + 4];
            a[3] = qh[(m + 8) * QH_STR + ku + tg + 4];
#pragma unroll
            for (int ni = 0; ni < 13; ni++) {
                int n = ni * 8 + g;
                uint32_t bf[2];
                bf[0] = kh[n * KH_STR + ku + tg];
                bf[1] = kh[n * KH_STR + ku + tg + 4];
                mma_f16(acc[ni], a, bf);
            }
        }
        const float scale = 0.125f;
#pragma unroll
        for (int ni = 0; ni < 13; ni++)
#pragma unroll
            for (int rr = 0; rr < 2; rr++) {
                int row = warp * 16 + rr * 8 + g;
                int col = ni * 8 + tg * 2;
                *(float2*)&sc[row * SCF_STR + col] =
                    make_float2(acc[ni][rr * 2] * scale, acc[ni][rr * 2 + 1] * scale);
            }
    }
    __syncthreads();

    // --- Softmax (fp32), writes P as fp16.
    for (int r = warp; r < S_; r += 8) {
        float v0 = (lane < S_) ? sc[r * SCF_STR + lane] : -1e30f;
        float v1 = sc[r * SCF_STR + lane + 32];
        float v2 = (lane + 64 < S_) ? sc[r * SCF_STR + lane + 64] : -1e30f;
        float v3 = (lane + 96 < S_) ? sc[r * SCF_STR + lane + 96] : -1e30f;
        float m = fmaxf(fmaxf(v0, v1), fmaxf(v2, v3));
#pragma unroll
        for (int off = 16; off > 0; off >>= 1)
            m = fmaxf(m, __shfl_xor_sync(0xffffffffu, m, off));
        float e0 = (lane < S_) ? __expf(v0 - m) : 0.f;
        float e1 = __expf(v1 - m);
        float e2 = (lane + 64 < S_) ? __expf(v2 - m) : 0.f;
        float e3 = (lane + 96 < S_) ? __expf(v3 - m) : 0.f;
        float s = e0 + e1 + e2 + e3;
#pragma unroll
        for (int off = 16; off > 0; off >>= 1)
            s += __shfl_xor_sync(0xffffffffu, s, off);
        float inv = 1.f / s;
        if (lane < S_) phh[r * (PH_STR * 2) + lane] = __float2half_rn(e0 * inv);
        phh[r * (PH_STR * 2) + lane + 32] = __float2half_rn(e1 * inv);
        if (lane + 64 < S_) phh[r * (PH_STR * 2) + lane + 64] = __float2half_rn(e2 * inv);
        if (lane + 96 < S_) phh[r * (PH_STR * 2) + lane + 96] = __float2half_rn(e3 * inv);
    }
    __syncthreads();

    // --- AV: m-tile per warp; 8 n-tiles (N=64); K=112 -> 7 k16 slices.
    if (warp < 7) {
        float acc[8][4];
#pragma unroll
        for (int ni = 0; ni < 8; ni++)
#pragma unroll
            for (int c = 0; c < 4; c++) acc[ni][c] = 0.f;
        int m = warp * 16 + g;
#pragma unroll
        for (int ks = 0; ks < 7; ks++) {
            int ku = ks * 8;
            uint32_t a[4];
            a[0] = ph[m * PH_STR + ku + tg];
            a[1] = ph[(m + 8) * PH_STR + ku + tg];
            a[2] = ph[m * PH_STR + ku + tg + 4];
            a[3] = ph[(m + 8) * PH_STR + ku + tg + 4];
#pragma unroll
            for (int ni = 0; ni < 8; ni++) {
                int n = ni * 8 + g;
                uint32_t bf[2];
                bf[0] = vt[n * VT_STR + ku + tg];
                bf[1] = vt[n * VT_STR + ku + tg + 4];
                mma_f16(acc[ni], a, bf);
            }
        }
        const size_t cbase = (size_t)b * S_ * D_ + (size_t)h * DEPTH_;
#pragma unroll
        for (int ni = 0; ni < 8; ni++)
#pragma unroll
            for (int rr = 0; rr < 2; rr++) {
                int row = warp * 16 + rr * 8 + g;
                if (row < S_) {
                    int col = ni * 8 + tg * 2;
                    *(__half2*)&ctx[cbase + (size_t)row * D_ + col] =
                        __floats2half2_rn(acc[ni][rr * 2], acc[ni][rr * 2 + 1]);
                }
            }
    }
}

// ---------------------------------------------------------------------------
// Fused split-K reduce + bias + residual + LayerNorm (optional fp16 twin).
// ---------------------------------------------------------------------------
template <bool HALF2>
__global__ __launch_bounds__(256)
void lnred_kernel(const float* __restrict__ p0, const float* __restrict__ p1,
                  const float* __restrict__ bias, const float* __restrict__ res,
                  const float* __restrict__ gamma, const float* __restrict__ beta,
                  float* __restrict__ out, __half* __restrict__ out_h) {
    int row = blockIdx.x;
    size_t base = (size_t)row * D_;
    int tid = threadIdx.x;

    float vals[4];
    float sum = 0.f, sq = 0.f;
#pragma unroll
    for (int r = 0; r < 4; r++) {
        int d = tid + r * 256;
        float v = p0[base + d] + p1[base + d] + bias[d] + res[base + d];
        vals[r] = v;
        sum += v;
        sq += v * v;
    }
#pragma unroll
    for (int off = 16; off > 0; off >>= 1) {
        sum += __shfl_xor_sync(0xffffffffu, sum, off);
        sq += __shfl_xor_sync(0xffffffffu, sq, off);
    }
    __shared__ float s1[8], s2[8];
    int wid = tid >> 5, lid = tid & 31;
    if (lid == 0) { s1[wid] = sum; s2[wid] = sq; }
    __syncthreads();
    if (wid == 0) {
        sum = (lid < 8) ? s1[lid] : 0.f;
        sq = (lid < 8) ? s2[lid] : 0.f;
#pragma unroll
        for (int off = 4; off > 0; off >>= 1) {
            sum += __shfl_xor_sync(0xffffffffu, sum, off);
            sq += __shfl_xor_sync(0xffffffffu, sq, off);
        }
        if (lid == 0) { s1[0] = sum; s2[0] = sq; }
    }
    __syncthreads();
    float mean = s1[0] * (1.0f / D_);
    float var = s2[0] * (1.0f / D_) - mean * mean;
    float inv = rsqrtf(var + EPS_);
#pragma unroll
    for (int r = 0; r < 4; r++) {
        int d = tid + r * 256;
        float o = gamma[d] * ((vals[r] - mean) * inv) + beta[d];
        out[base + d] = o;
        if (HALF2) out_h[base + d] = __float2half_rn(o);
    }
}

// ---------------------------------------------------------------------------
// Launch
// ---------------------------------------------------------------------------
extern "C" void kernel_launch(void* const* d_in, const int* in_sizes, int n_in,
                              void* d_out, int out_size) {
    const int* tokens = (const int*)d_in[0];
    const float* emb = (const float*)d_in[1];
    const float* Wq = (const float*)d_in[2];
    const float* bq = (const float*)d_in[3];
    const float* Wk = (const float*)d_in[4];
    const float* bk = (const float*)d_in[5];
    const float* Wv = (const float*)d_in[6];
    const float* bv = (const float*)d_in[7];
    const float* Wo = (const float*)d_in[8];
    const float* bo = (const float*)d_in[9];
    const float* W1 = (const float*)d_in[10];
    const float* b1 = (const float*)d_in[11];
    const float* W2 = (const float*)d_in[12];
    const float* b2 = (const float*)d_in[13];
    const float* gamma1 = (const float*)d_in[14];
    const float* beta1 = (const float*)d_in[15];
    const float* gamma2 = (const float*)d_in[16];
    const float* beta2 = (const float*)d_in[17];
    float* out = (float*)d_out;

    float *pe, *x, *bqkv, *t1, *x1;
    __half *xh, *WqkvTh, *WoTh, *W1Th, *W2Th, *QKVh, *ctxh, *x1h, *ffhh;
    cudaGetSymbolAddress((void**)&pe, g_pe);
    cudaGetSymbolAddress((void**)&x, g_x);
    cudaGetSymbolAddress((void**)&xh, g_xh);
    cudaGetSymbolAddress((void**)&WqkvTh, g_WqkvTh);
    cudaGetSymbolAddress((void**)&bqkv, g_bqkv);
    cudaGetSymbolAddress((void**)&WoTh, g_WoTh);
    cudaGetSymbolAddress((void**)&W1Th, g_W1Th);
    cudaGetSymbolAddress((void**)&W2Th, g_W2Th);
    cudaGetSymbolAddress((void**)&QKVh, g_QKVh);
    cudaGetSymbolAddress((void**)&ctxh, g_ctxh);
    cudaGetSymbolAddress((void**)&t1, g_t1);
    cudaGetSymbolAddress((void**)&x1, g_x1);
    cudaGetSymbolAddress((void**)&x1h, g_x1h);
    cudaGetSymbolAddress((void**)&ffhh, g_ffhh);

    cudaFuncSetAttribute(attention_kernel,
                         cudaFuncAttributeMaxDynamicSharedMemorySize, ATT_SMEM);
    cudaFuncSetAttribute(mma_gemm_h<0>,
                         cudaFuncAttributeMaxDynamicSharedMemorySize, SMEM_GEMM);
    cudaFuncSetAttribute(mma_gemm_h<9>,
                         cudaFuncAttributeMaxDynamicSharedMemorySize, SMEM_GEMM);
    cudaFuncSetAttribute(mma_gemm_h<11>,
                         cudaFuncAttributeMaxDynamicSharedMemorySize, SMEM_GEMM);

    // 1. positional encoding + embedding (+ bias concat folded in)
    pe_kernel<<<(S_ * D_ + 255) / 256, 256>>>(pe);
    embed_kernel<<<(BS_ * D_ / 4 + 255) / 256, 256>>>(tokens, emb, pe, x, xh,
                                                      bq, bk, bv, bqkv);

    // 2. weight prep: transpose to [N,K] fp16
    qkvT_kernel<<<dim3(2, 32, 48), dim3(32, 8)>>>(Wq, Wk, Wv, WqkvTh);
    transpose_half<<<dim3(32, 32), dim3(32, 8)>>>(Wo, WoTh, D_, D_);
    transpose_half<<<dim3(128, 32), dim3(32, 8)>>>(W1, W1Th, D_, F_);
    transpose_half<<<dim3(32, 128), dim3(32, 8)>>>(W2, W2Th, F_, D_);

    // 3. fused QKV projection (bias + fp16 output)
    mma_gemm_h<9><<<dim3(N_QKV / 128, BS_ / 128), 128, SMEM_GEMM>>>(
        xh, WqkvTh, QKVh, bqkv, nullptr, BS_, N_QKV, D_);

    // 4. attention (fp16 MMA; fp16 in/out)
    attention_kernel<<<B_ * H_, 256, ATT_SMEM>>>(QKVh, ctxh);

    // 5. output projection (split-K 2, fp32 partials) + fused reduce+LN1
    mma_gemm_h<0><<<dim3(D_ / 128, BS_ / 128, 2), 128, SMEM_GEMM>>>(
        ctxh, WoTh, t1, nullptr, nullptr, BS_, D_, D_);
    lnred_kernel<true><<<BS_, 256>>>(t1, t1 + (size_t)BS_ * D_, bo, x,
                                     gamma1, beta1, x1, x1h);

    // 6. FFN: W1 (bias+relu+fp16 out), W2 (split-K 2, fp32 partials)
    mma_gemm_h<11><<<dim3(F_ / 128, BS_ / 128), 128, SMEM_GEMM>>>(
        x1h, W1Th, ffhh, b1, nullptr, BS_, F_, D_);
    mma_gemm_h<0><<<dim3(D_ / 128, BS_ / 128, 2), 128, SMEM_GEMM>>>(
        ffhh, W2Th, t1, nullptr, nullptr, BS_, D_, F_);

    // 7. fused reduce + LN2 -> output
    lnred_kernel<false><<<BS_, 256>>>(t1, t1 + (size_t)BS_ * D_, b2, x1,
                                      gamma2, beta2, out, nullptr);
}

// round 13
// speedup vs baseline: 2.6941x; 1.0588x over previous
#include <cuda_runtime.h>
#include <cuda_fp16.h>
#include <math.h>
#include <stdint.h>

// Problem constants
#define B_ 64
#define S_ 100
#define D_ 1024
#define H_ 16
#define F_ 4096
#define DEPTH_ 64
#define BS_ (B_ * S_)          // 6400
#define N_QKV 3072
#define EPS_ 1e-6f

// ---------------------------------------------------------------------------
// Scratch (device globals; no allocations allowed)
// ---------------------------------------------------------------------------
__device__ float g_pe[S_ * D_];
__device__ float g_x[BS_ * D_];          // fp32 residual
__device__ __half g_xh[BS_ * D_];        // fp16 GEMM A operand
__device__ __half g_WqkvTh[N_QKV * D_];  // [N,K] fp16
__device__ float g_bqkv[N_QKV];
__device__ __half g_WoTh[D_ * D_];       // [N,K] fp16
__device__ __half g_W1Th[F_ * D_];       // [N,K] fp16
__device__ __half g_W2Th[D_ * F_];       // [N,K] fp16
__device__ __half g_QKVh[BS_ * N_QKV];   // fp16 QKV
__device__ __half g_ctxh[BS_ * D_];      // fp16 attention output
__device__ float g_t1[2 * BS_ * D_];     // split-K fp32 partials
__device__ float g_x1[BS_ * D_];         // fp32 residual
__device__ __half g_x1h[BS_ * D_];       // fp16 twin
__device__ __half g_ffhh[BS_ * F_];      // fp16 relu output

__device__ __forceinline__ void mma_f16(float* d, const uint32_t* a, const uint32_t* b) {
    asm volatile(
        "mma.sync.aligned.m16n8k16.row.col.f32.f16.f16.f32 "
        "{%0,%1,%2,%3}, {%4,%5,%6,%7}, {%8,%9}, {%0,%1,%2,%3};\n"
        : "+f"(d[0]), "+f"(d[1]), "+f"(d[2]), "+f"(d[3])
        : "r"(a[0]), "r"(a[1]), "r"(a[2]), "r"(a[3]), "r"(b[0]), "r"(b[1]));
}

// ---------------------------------------------------------------------------
// Positional encoding (fp64 to match numpy float64 table)
// ---------------------------------------------------------------------------
__global__ void pe_kernel(float* __restrict__ pe) {
    int idx = blockIdx.x * blockDim.x + threadIdx.x;
    if (idx >= S_ * D_) return;
    int s = idx / D_;
    int d = idx % D_;
    int k2 = d & ~1;
    double div = pow(10000.0, (double)k2 / (double)D_);
    double arg = (double)s / div;
    pe[idx] = (float)((d & 1) ? cos(arg) : sin(arg));
}

// ---------------------------------------------------------------------------
// Embedding gather + positional add; fp32 x, fp16 xh. Also concats QKV bias.
// ---------------------------------------------------------------------------
__global__ void embed_kernel(const int* __restrict__ tokens,
                             const float* __restrict__ emb,
                             const float* __restrict__ pe,
                             float* __restrict__ x, __half* __restrict__ xh,
                             const float* __restrict__ bq, const float* __restrict__ bk,
                             const float* __restrict__ bv, float* __restrict__ bqkv) {
    int idx = blockIdx.x * blockDim.x + threadIdx.x;
    if (idx < N_QKV) {
        int which = idx / D_;
        int n = idx % D_;
        const float* bb = (which == 0) ? bq : ((which == 1) ? bk : bv);
        bqkv[idx] = bb[n];
    }
    if (idx >= BS_ * D_ / 4) return;
    int row = idx / (D_ / 4);
    int c4 = idx % (D_ / 4);
    int tok = tokens[row];
    float4 e = ((const float4*)(emb + (size_t)tok * D_))[c4];
    float4 p = ((const float4*)(pe + (size_t)(row % S_) * D_))[c4];
    float4 o;
    o.x = e.x + p.x; o.y = e.y + p.y; o.z = e.z + p.z; o.w = e.w + p.w;
    ((float4*)x)[idx] = o;
    ((__half2*)xh)[idx * 2 + 0] = __floats2half2_rn(o.x, o.y);
    ((__half2*)xh)[idx * 2 + 1] = __floats2half2_rn(o.z, o.w);
}

// ---------------------------------------------------------------------------
// QKV weight transpose: W{q,k,v}[H,D,64] -> WqkvTh[3072, 1024] fp16 ([N,K])
// ---------------------------------------------------------------------------
__global__ void qkvT_kernel(const float* __restrict__ Wq, const float* __restrict__ Wk,
                            const float* __restrict__ Wv, __half* __restrict__ Wt) {
    __shared__ float t[32][33];
    int z = blockIdx.z;
    int which = z / H_, h = z % H_;
    const float* W = (which == 0) ? Wq : ((which == 1) ? Wk : Wv);
    const float* src = W + (size_t)h * D_ * DEPTH_;
    int e0 = blockIdx.x * 32, d0 = blockIdx.y * 32;
    int tx = threadIdx.x, ty = threadIdx.y;
    for (int i = ty; i < 32; i += 8)
        t[i][tx] = src[(size_t)(d0 + i) * DEPTH_ + e0 + tx];
    __syncthreads();
    __half* dst = Wt + ((size_t)which * D_ + h * DEPTH_) * D_;
    for (int i = ty; i < 32; i += 8)
        dst[(size_t)(e0 + i) * D_ + d0 + tx] = __float2half_rn(t[tx][i]);
}

// ---------------------------------------------------------------------------
// Tiled transpose + fp16 convert: src[R,C] f32 -> dst[C,R] f16.
// ---------------------------------------------------------------------------
__global__ void transpose_half(const float* __restrict__ src, __half* __restrict__ dst,
                               int R, int C) {
    __shared__ float t[32][33];
    int c0 = blockIdx.x * 32, r0 = blockIdx.y * 32;
    int tx = threadIdx.x, ty = threadIdx.y;
    for (int i = ty; i < 32; i += 8)
        t[i][tx] = src[(size_t)(r0 + i) * C + c0 + tx];
    __syncthreads();
    for (int i = ty; i < 32; i += 8)
        dst[(size_t)(c0 + i) * R + r0 + tx] = __float2half_rn(t[tx][i]);
}

// ---------------------------------------------------------------------------
// FP16 mma.sync GEMM (unchanged from best).
// ---------------------------------------------------------------------------
#define STRH 20
#define TILEU (128 * STRH)
#define STAGEU (2 * TILEU)
#define SMEM_GEMM (2 * STAGEU * 4)

template <int EPI>
__global__ __launch_bounds__(128, 3)
void mma_gemm_h(const __half* __restrict__ A, const __half* __restrict__ Bt,
                void* __restrict__ Cv, const float* __restrict__ bias,
                const float* __restrict__ res, int M, int N, int K) {
    extern __shared__ uint32_t smu[];
    int tid = threadIdx.x;
    int lane = tid & 31, warp = tid >> 5;
    int wm = warp & 1, wn = warp >> 1;
    int g = lane >> 2, tg = lane & 3;
    int bm = blockIdx.y * 128, bn = blockIdx.x * 128;

    int kspl = K / gridDim.z;
    int kOff = blockIdx.z * kspl;
    A += kOff;
    Bt += kOff;
    float* Cf = (float*)Cv + (size_t)blockIdx.z * M * N;
    __half* Ch = (__half*)Cv;

    float acc[4][8][4];
#pragma unroll
    for (int i = 0; i < 4; i++)
#pragma unroll
        for (int j = 0; j < 8; j++)
#pragma unroll
            for (int c = 0; c < 4; c++) acc[i][j][c] = 0.f;

    const int KT = kspl / 32;

    int pr = tid >> 2, pc = tid & 3;
    const __half* aSrc = A + (size_t)(bm + pr) * K + pc * 8;
    const __half* bSrc = Bt + (size_t)(bn + pr) * K + pc * 8;
    uint32_t smemBase = (uint32_t)__cvta_generic_to_shared(smu);
    uint32_t aDst0 = smemBase + (uint32_t)(pr * 80 + pc * 16);
    uint32_t bDst0 = smemBase + TILEU * 4 + (uint32_t)(pr * 80 + pc * 16);

    auto prefetch = [&](int stage) {
        uint32_t so = (uint32_t)(stage * STAGEU * 4);
#pragma unroll
        for (int q = 0; q < 4; q++) {
            uint32_t dst = aDst0 + so + (uint32_t)(q * 32 * 80);
            const __half* src = aSrc + (size_t)(q * 32) * K;
            asm volatile("cp.async.cg.shared.global [%0], [%1], 16;" :: "r"(dst), "l"(src));
        }
#pragma unroll
        for (int q = 0; q < 4; q++) {
            uint32_t dst = bDst0 + so + (uint32_t)(q * 32 * 80);
            const __half* src = bSrc + (size_t)(q * 32) * K;
            asm volatile("cp.async.cg.shared.global [%0], [%1], 16;" :: "r"(dst), "l"(src));
        }
        aSrc += 32;
        bSrc += 32;
    };

    prefetch(0);
    asm volatile("cp.async.commit_group;");

    for (int kt = 0; kt < KT; kt++) {
        if (kt + 1 < KT) prefetch((kt + 1) & 1);
        asm volatile("cp.async.commit_group;");
        asm volatile("cp.async.wait_group 1;");
        __syncthreads();

        const uint32_t* As = smu + (kt & 1) * STAGEU;
        const uint32_t* Bs = As + TILEU;
#pragma unroll
        for (int ks = 0; ks < 2; ks++) {
            int ku = ks * 8;
            uint32_t afr[4][4];
#pragma unroll
            for (int mi = 0; mi < 4; mi++) {
                int m = wm * 64 + mi * 16 + g;
                afr[mi][0] = As[m * STRH + ku + tg];
                afr[mi][1] = As[(m + 8) * STRH + ku + tg];
                afr[mi][2] = As[m * STRH + ku + tg + 4];
                afr[mi][3] = As[(m + 8) * STRH + ku + tg + 4];
            }
            uint32_t bfr[8][2];
#pragma unroll
            for (int ni = 0; ni < 8; ni++) {
                int n = wn * 64 + ni * 8 + g;
                bfr[ni][0] = Bs[n * STRH + ku + tg];
                bfr[ni][1] = Bs[n * STRH + ku + tg + 4];
            }
#pragma unroll
            for (int mi = 0; mi < 4; mi++)
#pragma unroll
                for (int ni = 0; ni < 8; ni++)
                    mma_f16(acc[mi][ni], afr[mi], bfr[ni]);
        }
        __syncthreads();
    }

#pragma unroll
    for (int mi = 0; mi < 4; mi++) {
#pragma unroll
        for (int rr = 0; rr < 2; rr++) {
            int row = bm + wm * 64 + mi * 16 + rr * 8 + g;
#pragma unroll
            for (int ni = 0; ni < 8; ni++) {
                int col = bn + wn * 64 + ni * 8 + tg * 2;
                float vx = acc[mi][ni][rr * 2 + 0];
                float vy = acc[mi][ni][rr * 2 + 1];
                if (EPI & 1) { vx += bias[col]; vy += bias[col + 1]; }
                if (EPI & 4) {
                    const float* rp = res + (size_t)row * N + col;
                    vx += rp[0]; vy += rp[1];
                }
                if (EPI & 2) { vx = fmaxf(vx, 0.f); vy = fmaxf(vy, 0.f); }
                if (EPI & 8) {
                    *(__half2*)&Ch[(size_t)row * N + col] = __floats2half2_rn(vx, vy);
                } else {
                    *(float2*)&Cf[(size_t)row * N + col] = make_float2(vx, vy);
                }
            }
        }
    }
}

// ---------------------------------------------------------------------------
// Fused attention per (b, h) — fp16 MMAs + register-resident softmax.
// Smem (u32): qh [112][36], kh [112][36], vt [64][60]. 47.6 KB total.
// QK acc fragments are reduced in-register (quad shfl) and converted
// directly into AV A-operand fragments (layouts coincide). No sc/ph smem.
// Only vt is zero-filled (its pad cols multiply nonzero P-register values).
// ---------------------------------------------------------------------------
#define QH_STR 36
#define KH_STR 36
#define VT_STR 60
#define QH_OFF 0
#define KH_OFF (QH_OFF + 112 * QH_STR)
#define VT_OFF (KH_OFF + 112 * KH_STR)
#define ATT_U32 (VT_OFF + 64 * VT_STR)
#define ATT_SMEM (ATT_U32 * 4)   // 47616 bytes

__global__ __launch_bounds__(256)
void attention_kernel(const __half* __restrict__ QKV, __half* __restrict__ ctx) {
    extern __shared__ uint32_t su[];
    uint32_t* qh = su + QH_OFF;
    uint32_t* kh = su + KH_OFF;
    uint32_t* vt = su + VT_OFF;
    __half* vth = (__half*)vt;

    int bh = blockIdx.x;
    int b = bh / H_;
    int h = bh % H_;
    int tid = threadIdx.x;
    int lane = tid & 31, warp = tid >> 5;
    int g = lane >> 2, tg = lane & 3;

    // Zero vt only (pads multiply real P values; qh/kh pads feed discarded rows).
    for (int i = tid; i < 64 * VT_STR; i += 256) vt[i] = 0;
    __syncthreads();

    // Load q, k (u32 copies, natural [s][e] layout) and v transposed [e][s].
    for (int i = tid; i < S_ * 16; i += 256) {
        int s = i >> 4, e4 = (i & 15) * 4;
        size_t off = ((size_t)(b * S_ + s)) * N_QKV + h * DEPTH_ + e4;
        qh[s * QH_STR + e4 / 2] = *(const uint32_t*)(QKV + off);
        qh[s * QH_STR + e4 / 2 + 1] = *(const uint32_t*)(QKV + off + 2);
        kh[s * KH_STR + e4 / 2] = *(const uint32_t*)(QKV + off + D_);
        kh[s * KH_STR + e4 / 2 + 1] = *(const uint32_t*)(QKV + off + D_ + 2);
        __half2 v01 = *(const __half2*)(QKV + off + 2 * D_);
        __half2 v23 = *(const __half2*)(QKV + off + 2 * D_ + 2);
        vth[(e4 + 0) * (VT_STR * 2) + s] = __low2half(v01);
        vth[(e4 + 1) * (VT_STR * 2) + s] = __high2half(v01);
        vth[(e4 + 2) * (VT_STR * 2) + s] = __low2half(v23);
        vth[(e4 + 3) * (VT_STR * 2) + s] = __high2half(v23);
    }
    __syncthreads();

    if (warp >= 7) return;

    // --- QK^T: m-tile per warp; 13 n-tiles; K=64 -> 4 k16 slices.
    float acc[13][4];
#pragma unroll
    for (int ni = 0; ni < 13; ni++)
#pragma unroll
        for (int c = 0; c < 4; c++) acc[ni][c] = 0.f;
    {
        int m = warp * 16 + g;
#pragma unroll
        for (int ks = 0; ks < 4; ks++) {
            int ku = ks * 8;
            uint32_t a[4];
            a[0] = qh[m * QH_STR + ku + tg];
            a[1] = qh[(m + 8) * QH_STR + ku + tg];
            a[2] = qh[m * QH_STR + ku + tg + 4];
            a[3] = qh[(m + 8) * QH_STR + ku + tg + 4];
#pragma unroll
            for (int ni = 0; ni < 13; ni++) {
                int n = ni * 8 + g;
                uint32_t bf[2];
                bf[0] = kh[n * KH_STR + ku + tg];
                bf[1] = kh[n * KH_STR + ku + tg + 4];
                mma_f16(acc[ni], a, bf);
            }
        }
    }

    // --- Register softmax. Row r handled by quad (fixed g), tg spans cols.
    // col(ni, j) = ni*8 + 2*tg + j. Valid iff col < 100.
    const float scale = 0.125f;
    float p[13][4];
#pragma unroll
    for (int rr = 0; rr < 2; rr++) {
        float m = -1e30f;
#pragma unroll
        for (int ni = 0; ni < 13; ni++) {
#pragma unroll
            for (int j = 0; j < 2; j++) {
                int col = ni * 8 + 2 * tg + j;
                if (col < S_) {
                    float v = acc[ni][rr * 2 + j] * scale;
                    m = fmaxf(m, v);
                }
            }
        }
        m = fmaxf(m, __shfl_xor_sync(0xffffffffu, m, 1));
        m = fmaxf(m, __shfl_xor_sync(0xffffffffu, m, 2));
        float sum = 0.f;
#pragma unroll
        for (int ni = 0; ni < 13; ni++) {
#pragma unroll
            for (int j = 0; j < 2; j++) {
                int col = ni * 8 + 2 * tg + j;
                float e = 0.f;
                if (col < S_) e = __expf(acc[ni][rr * 2 + j] * scale - m);
                p[ni][rr * 2 + j] = e;
                sum += e;
            }
        }
        sum += __shfl_xor_sync(0xffffffffu, sum, 1);
        sum += __shfl_xor_sync(0xffffffffu, sum, 2);
        float inv = 1.f / sum;
#pragma unroll
        for (int ni = 0; ni < 13; ni++) {
            p[ni][rr * 2 + 0] *= inv;
            p[ni][rr * 2 + 1] *= inv;
        }
    }

    // --- AV: P fragments straight from registers; 8 n-tiles; 7 k16 slices.
    float oacc[8][4];
#pragma unroll
    for (int ni = 0; ni < 8; ni++)
#pragma unroll
        for (int c = 0; c < 4; c++) oacc[ni][c] = 0.f;
#pragma unroll
    for (int ks = 0; ks < 7; ks++) {
        uint32_t a[4];
        __half2 h0 = __floats2half2_rn(p[2 * ks][0], p[2 * ks][1]);
        __half2 h1 = __floats2half2_rn(p[2 * ks][2], p[2 * ks][3]);
        a[0] = *(uint32_t*)&h0;
        a[1] = *(uint32_t*)&h1;
        if (ks < 6) {
            __half2 h2 = __floats2half2_rn(p[2 * ks + 1][0], p[2 * ks + 1][1]);
            __half2 h3 = __floats2half2_rn(p[2 * ks + 1][2], p[2 * ks + 1][3]);
            a[2] = *(uint32_t*)&h2;
            a[3] = *(uint32_t*)&h3;
        } else {
            a[2] = 0;
            a[3] = 0;
        }
        int ku = ks * 8;
#pragma unroll
        for (int ni = 0; ni < 8; ni++) {
            int n = ni * 8 + g;
            uint32_t bf[2];
            bf[0] = vt[n * VT_STR + ku + tg];
            bf[1] = vt[n * VT_STR + ku + tg + 4];
            mma_f16(oacc[ni], a, bf);
        }
    }

    const size_t cbase = (size_t)b * S_ * D_ + (size_t)h * DEPTH_;
#pragma unroll
    for (int ni = 0; ni < 8; ni++)
#pragma unroll
        for (int rr = 0; rr < 2; rr++) {
            int row = warp * 16 + rr * 8 + g;
            if (row < S_) {
                int col = ni * 8 + tg * 2;
                *(__half2*)&ctx[cbase + (size_t)row * D_ + col] =
                    __floats2half2_rn(oacc[ni][rr * 2], oacc[ni][rr * 2 + 1]);
            }
        }
}

// ---------------------------------------------------------------------------
// Fused split-K reduce + bias + residual + LayerNorm (optional fp16 twin).
// ---------------------------------------------------------------------------
template <bool HALF2>
__global__ __launch_bounds__(256)
void lnred_kernel(const float* __restrict__ p0, const float* __restrict__ p1,
                  const float* __restrict__ bias, const float* __restrict__ res,
                  const float* __restrict__ gamma, const float* __restrict__ beta,
                  float* __restrict__ out, __half* __restrict__ out_h) {
    int row = blockIdx.x;
    size_t base = (size_t)row * D_;
    int tid = threadIdx.x;

    float vals[4];
    float sum = 0.f, sq = 0.f;
#pragma unroll
    for (int r = 0; r < 4; r++) {
        int d = tid + r * 256;
        float v = p0[base + d] + p1[base + d] + bias[d] + res[base + d];
        vals[r] = v;
        sum += v;
        sq += v * v;
    }
#pragma unroll
    for (int off = 16; off > 0; off >>= 1) {
        sum += __shfl_xor_sync(0xffffffffu, sum, off);
        sq += __shfl_xor_sync(0xffffffffu, sq, off);
    }
    __shared__ float s1[8], s2[8];
    int wid = tid >> 5, lid = tid & 31;
    if (lid == 0) { s1[wid] = sum; s2[wid] = sq; }
    __syncthreads();
    if (wid == 0) {
        sum = (lid < 8) ? s1[lid] : 0.f;
        sq = (lid < 8) ? s2[lid] : 0.f;
#pragma unroll
        for (int off = 4; off > 0; off >>= 1) {
            sum += __shfl_xor_sync(0xffffffffu, sum, off);
            sq += __shfl_xor_sync(0xffffffffu, sq, off);
        }
        if (lid == 0) { s1[0] = sum; s2[0] = sq; }
    }
    __syncthreads();
    float mean = s1[0] * (1.0f / D_);
    float var = s2[0] * (1.0f / D_) - mean * mean;
    float inv = rsqrtf(var + EPS_);
#pragma unroll
    for (int r = 0; r < 4; r++) {
        int d = tid + r * 256;
        float o = gamma[d] * ((vals[r] - mean) * inv) + beta[d];
        out[base + d] = o;
        if (HALF2) out_h[base + d] = __float2half_rn(o);
    }
}

// ---------------------------------------------------------------------------
// Launch
// ---------------------------------------------------------------------------
extern "C" void kernel_launch(void* const* d_in, const int* in_sizes, int n_in,
                              void* d_out, int out_size) {
    const int* tokens = (const int*)d_in[0];
    const float* emb = (const float*)d_in[1];
    const float* Wq = (const float*)d_in[2];
    const float* bq = (const float*)d_in[3];
    const float* Wk = (const float*)d_in[4];
    const float* bk = (const float*)d_in[5];
    const float* Wv = (const float*)d_in[6];
    const float* bv = (const float*)d_in[7];
    const float* Wo = (const float*)d_in[8];
    const float* bo = (const float*)d_in[9];
    const float* W1 = (const float*)d_in[10];
    const float* b1 = (const float*)d_in[11];
    const float* W2 = (const float*)d_in[12];
    const float* b2 = (const float*)d_in[13];
    const float* gamma1 = (const float*)d_in[14];
    const float* beta1 = (const float*)d_in[15];
    const float* gamma2 = (const float*)d_in[16];
    const float* beta2 = (const float*)d_in[17];
    float* out = (float*)d_out;

    float *pe, *x, *bqkv, *t1, *x1;
    __half *xh, *WqkvTh, *WoTh, *W1Th, *W2Th, *QKVh, *ctxh, *x1h, *ffhh;
    cudaGetSymbolAddress((void**)&pe, g_pe);
    cudaGetSymbolAddress((void**)&x, g_x);
    cudaGetSymbolAddress((void**)&xh, g_xh);
    cudaGetSymbolAddress((void**)&WqkvTh, g_WqkvTh);
    cudaGetSymbolAddress((void**)&bqkv, g_bqkv);
    cudaGetSymbolAddress((void**)&WoTh, g_WoTh);
    cudaGetSymbolAddress((void**)&W1Th, g_W1Th);
    cudaGetSymbolAddress((void**)&W2Th, g_W2Th);
    cudaGetSymbolAddress((void**)&QKVh, g_QKVh);
    cudaGetSymbolAddress((void**)&ctxh, g_ctxh);
    cudaGetSymbolAddress((void**)&t1, g_t1);
    cudaGetSymbolAddress((void**)&x1, g_x1);
    cudaGetSymbolAddress((void**)&x1h, g_x1h);
    cudaGetSymbolAddress((void**)&ffhh, g_ffhh);

    cudaFuncSetAttribute(attention_kernel,
                         cudaFuncAttributeMaxDynamicSharedMemorySize, ATT_SMEM);
    cudaFuncSetAttribute(mma_gemm_h<0>,
                         cudaFuncAttributeMaxDynamicSharedMemorySize, SMEM_GEMM);
    cudaFuncSetAttribute(mma_gemm_h<9>,
                         cudaFuncAttributeMaxDynamicSharedMemorySize, SMEM_GEMM);
    cudaFuncSetAttribute(mma_gemm_h<11>,
                         cudaFuncAttributeMaxDynamicSharedMemorySize, SMEM_GEMM);

    // 1. positional encoding + embedding (+ bias concat folded in)
    pe_kernel<<<(S_ * D_ + 255) / 256, 256>>>(pe);
    embed_kernel<<<(BS_ * D_ / 4 + 255) / 256, 256>>>(tokens, emb, pe, x, xh,
                                                      bq, bk, bv, bqkv);

    // 2. weight prep: transpose to [N,K] fp16
    qkvT_kernel<<<dim3(2, 32, 48), dim3(32, 8)>>>(Wq, Wk, Wv, WqkvTh);
    transpose_half<<<dim3(32, 32), dim3(32, 8)>>>(Wo, WoTh, D_, D_);
    transpose_half<<<dim3(128, 32), dim3(32, 8)>>>(W1, W1Th, D_, F_);
    transpose_half<<<dim3(32, 128), dim3(32, 8)>>>(W2, W2Th, F_, D_);

    // 3. fused QKV projection (bias + fp16 output)
    mma_gemm_h<9><<<dim3(N_QKV / 128, BS_ / 128), 128, SMEM_GEMM>>>(
        xh, WqkvTh, QKVh, bqkv, nullptr, BS_, N_QKV, D_);

    // 4. attention (fp16 MMA, register softmax)
    attention_kernel<<<B_ * H_, 256, ATT_SMEM>>>(QKVh, ctxh);

    // 5. output projection (split-K 2, fp32 partials) + fused reduce+LN1
    mma_gemm_h<0><<<dim3(D_ / 128, BS_ / 128, 2), 128, SMEM_GEMM>>>(
        ctxh, WoTh, t1, nullptr, nullptr, BS_, D_, D_);
    lnred_kernel<true><<<BS_, 256>>>(t1, t1 + (size_t)BS_ * D_, bo, x,
                                     gamma1, beta1, x1, x1h);

    // 6. FFN: W1 (bias+relu+fp16 out), W2 (split-K 2, fp32 partials)
    mma_gemm_h<11><<<dim3(F_ / 128, BS_ / 128), 128, SMEM_GEMM>>>(
        x1h, W1Th, ffhh, b1, nullptr, BS_, F_, D_);
    mma_gemm_h<0><<<dim3(D_ / 128, BS_ / 128, 2), 128, SMEM_GEMM>>>(
        ffhh, W2Th, t1, nullptr, nullptr, BS_, D_, F_);

    // 7. fused reduce + LN2 -> output
    lnred_kernel<false><<<BS_, 256>>>(t1, t1 + (size_t)BS_ * D_, b2, x1,
                                      gamma2, beta2, out, nullptr);
}

// round 15
// speedup vs baseline: 2.8146x; 1.0447x over previous
#include <cuda_runtime.h>
#include <cuda_fp16.h>
#include <math.h>
#include <stdint.h>

// Problem constants
#define B_ 64
#define S_ 100
#define D_ 1024
#define H_ 16
#define F_ 4096
#define DEPTH_ 64
#define BS_ (B_ * S_)          // 6400
#define N_QKV 3072
#define EPS_ 1e-6f

// ---------------------------------------------------------------------------
// Scratch (device globals; no allocations allowed)
// ---------------------------------------------------------------------------
__device__ float g_pe[S_ * D_];
__device__ float g_x[BS_ * D_];          // fp32 residual
__device__ __half g_xh[BS_ * D_];        // fp16 GEMM A operand
__device__ __half g_WqkvTh[N_QKV * D_];  // [N,K] fp16
__device__ float g_bqkv[N_QKV];
__device__ __half g_WoTh[D_ * D_];       // [N,K] fp16
__device__ __half g_W1Th[F_ * D_];       // [N,K] fp16
__device__ __half g_W2Th[D_ * F_];       // [N,K] fp16
__device__ __half g_QKVh[BS_ * N_QKV];   // fp16 QKV
__device__ __half g_ctxh[BS_ * D_];      // fp16 attention output
__device__ float g_t1[2 * BS_ * D_];     // split-K fp32 partials
__device__ float g_x1[BS_ * D_];         // fp32 residual
__device__ __half g_x1h[BS_ * D_];       // fp16 twin
__device__ __half g_ffhh[BS_ * F_];      // fp16 relu output

__device__ __forceinline__ void mma_f16(float* d, const uint32_t* a, const uint32_t* b) {
    asm volatile(
        "mma.sync.aligned.m16n8k16.row.col.f32.f16.f16.f32 "
        "{%0,%1,%2,%3}, {%4,%5,%6,%7}, {%8,%9}, {%0,%1,%2,%3};\n"
        : "+f"(d[0]), "+f"(d[1]), "+f"(d[2]), "+f"(d[3])
        : "r"(a[0]), "r"(a[1]), "r"(a[2]), "r"(a[3]), "r"(b[0]), "r"(b[1]));
}

// ---------------------------------------------------------------------------
// Positional encoding (fp32). log2(10000) = 13.287712379549449.
// ---------------------------------------------------------------------------
__global__ void pe_kernel(float* __restrict__ pe) {
    int idx = blockIdx.x * blockDim.x + threadIdx.x;
    if (idx >= S_ * D_) return;
    int s = idx / D_;
    int d = idx % D_;
    int k2 = d & ~1;
    float div = exp2f((float)k2 * (13.2877123795494f / (float)D_));
    float arg = (float)s / div;
    pe[idx] = (d & 1) ? cosf(arg) : sinf(arg);
}

// ---------------------------------------------------------------------------
// Embedding gather + positional add; fp32 x, fp16 xh. Also concats QKV bias.
// ---------------------------------------------------------------------------
__global__ void embed_kernel(const int* __restrict__ tokens,
                             const float* __restrict__ emb,
                             const float* __restrict__ pe,
                             float* __restrict__ x, __half* __restrict__ xh,
                             const float* __restrict__ bq, const float* __restrict__ bk,
                             const float* __restrict__ bv, float* __restrict__ bqkv) {
    int idx = blockIdx.x * blockDim.x + threadIdx.x;
    if (idx < N_QKV) {
        int which = idx / D_;
        int n = idx % D_;
        const float* bb = (which == 0) ? bq : ((which == 1) ? bk : bv);
        bqkv[idx] = bb[n];
    }
    if (idx >= BS_ * D_ / 4) return;
    int row = idx / (D_ / 4);
    int c4 = idx % (D_ / 4);
    int tok = tokens[row];
    float4 e = ((const float4*)(emb + (size_t)tok * D_))[c4];
    float4 p = ((const float4*)(pe + (size_t)(row % S_) * D_))[c4];
    float4 o;
    o.x = e.x + p.x; o.y = e.y + p.y; o.z = e.z + p.z; o.w = e.w + p.w;
    ((float4*)x)[idx] = o;
    ((__half2*)xh)[idx * 2 + 0] = __floats2half2_rn(o.x, o.y);
    ((__half2*)xh)[idx * 2 + 1] = __floats2half2_rn(o.z, o.w);
}

// ---------------------------------------------------------------------------
// QKV weight transpose: W{q,k,v}[H,D,64] -> WqkvTh[3072, 1024] fp16 ([N,K])
// ---------------------------------------------------------------------------
__global__ void qkvT_kernel(const float* __restrict__ Wq, const float* __restrict__ Wk,
                            const float* __restrict__ Wv, __half* __restrict__ Wt) {
    __shared__ float t[32][33];
    int z = blockIdx.z;
    int which = z / H_, h = z % H_;
    const float* W = (which == 0) ? Wq : ((which == 1) ? Wk : Wv);
    const float* src = W + (size_t)h * D_ * DEPTH_;
    int e0 = blockIdx.x * 32, d0 = blockIdx.y * 32;
    int tx = threadIdx.x, ty = threadIdx.y;
    for (int i = ty; i < 32; i += 8)
        t[i][tx] = src[(size_t)(d0 + i) * DEPTH_ + e0 + tx];
    __syncthreads();
    __half* dst = Wt + ((size_t)which * D_ + h * DEPTH_) * D_;
    for (int i = ty; i < 32; i += 8)
        dst[(size_t)(e0 + i) * D_ + d0 + tx] = __float2half_rn(t[tx][i]);
}

// ---------------------------------------------------------------------------
// Merged transpose of Wo (1024x1024), W1 (1024x4096), W2 (4096x1024) -> fp16.
// 9216 32x32 tiles; block (32,8).
//   bid in [0, 1024)      : Wo
//   bid in [1024, 5120)   : W1
//   bid in [5120, 9216)   : W2
// ---------------------------------------------------------------------------
__global__ void transpose_all(const float* __restrict__ Wo, __half* __restrict__ WoT,
                              const float* __restrict__ W1, __half* __restrict__ W1T,
                              const float* __restrict__ W2, __half* __restrict__ W2T) {
    __shared__ float t[32][33];
    int bid = blockIdx.x;
    const float* src;
    __half* dst;
    int R, C, ti;
    if (bid < 1024) {
        src = Wo; dst = WoT; R = D_; C = D_; ti = bid;
    } else if (bid < 5120) {
        src = W1; dst = W1T; R = D_; C = F_; ti = bid - 1024;
    } else {
        src = W2; dst = W2T; R = F_; C = D_; ti = bid - 5120;
    }
    int tilesX = C / 32;
    int r0 = (ti / tilesX) * 32, c0 = (ti % tilesX) * 32;
    int tx = threadIdx.x, ty = threadIdx.y;
    for (int i = ty; i < 32; i += 8)
        t[i][tx] = src[(size_t)(r0 + i) * C + c0 + tx];
    __syncthreads();
    for (int i = ty; i < 32; i += 8)
        dst[(size_t)(c0 + i) * R + r0 + tx] = __float2half_rn(t[tx][i]);
}

// ---------------------------------------------------------------------------
// FP16 mma.sync GEMM (unchanged from best).
// ---------------------------------------------------------------------------
#define STRH 20
#define TILEU (128 * STRH)
#define STAGEU (2 * TILEU)
#define SMEM_GEMM (2 * STAGEU * 4)

template <int EPI>
__global__ __launch_bounds__(128, 3)
void mma_gemm_h(const __half* __restrict__ A, const __half* __restrict__ Bt,
                void* __restrict__ Cv, const float* __restrict__ bias,
                const float* __restrict__ res, int M, int N, int K) {
    extern __shared__ uint32_t smu[];
    int tid = threadIdx.x;
    int lane = tid & 31, warp = tid >> 5;
    int wm = warp & 1, wn = warp >> 1;
    int g = lane >> 2, tg = lane & 3;
    int bm = blockIdx.y * 128, bn = blockIdx.x * 128;

    int kspl = K / gridDim.z;
    int kOff = blockIdx.z * kspl;
    A += kOff;
    Bt += kOff;
    float* Cf = (float*)Cv + (size_t)blockIdx.z * M * N;
    __half* Ch = (__half*)Cv;

    float acc[4][8][4];
#pragma unroll
    for (int i = 0; i < 4; i++)
#pragma unroll
        for (int j = 0; j < 8; j++)
#pragma unroll
            for (int c = 0; c < 4; c++) acc[i][j][c] = 0.f;

    const int KT = kspl / 32;

    int pr = tid >> 2, pc = tid & 3;
    const __half* aSrc = A + (size_t)(bm + pr) * K + pc * 8;
    const __half* bSrc = Bt + (size_t)(bn + pr) * K + pc * 8;
    uint32_t smemBase = (uint32_t)__cvta_generic_to_shared(smu);
    uint32_t aDst0 = smemBase + (uint32_t)(pr * 80 + pc * 16);
    uint32_t bDst0 = smemBase + TILEU * 4 + (uint32_t)(pr * 80 + pc * 16);

    auto prefetch = [&](int stage) {
        uint32_t so = (uint32_t)(stage * STAGEU * 4);
#pragma unroll
        for (int q = 0; q < 4; q++) {
            uint32_t dst = aDst0 + so + (uint32_t)(q * 32 * 80);
            const __half* src = aSrc + (size_t)(q * 32) * K;
            asm volatile("cp.async.cg.shared.global [%0], [%1], 16;" :: "r"(dst), "l"(src));
        }
#pragma unroll
        for (int q = 0; q < 4; q++) {
            uint32_t dst = bDst0 + so + (uint32_t)(q * 32 * 80);
            const __half* src = bSrc + (size_t)(q * 32) * K;
            asm volatile("cp.async.cg.shared.global [%0], [%1], 16;" :: "r"(dst), "l"(src));
        }
        aSrc += 32;
        bSrc += 32;
    };

    prefetch(0);
    asm volatile("cp.async.commit_group;");

    for (int kt = 0; kt < KT; kt++) {
        if (kt + 1 < KT) prefetch((kt + 1) & 1);
        asm volatile("cp.async.commit_group;");
        asm volatile("cp.async.wait_group 1;");
        __syncthreads();

        const uint32_t* As = smu + (kt & 1) * STAGEU;
        const uint32_t* Bs = As + TILEU;
#pragma unroll
        for (int ks = 0; ks < 2; ks++) {
            int ku = ks * 8;
            uint32_t afr[4][4];
#pragma unroll
            for (int mi = 0; mi < 4; mi++) {
                int m = wm * 64 + mi * 16 + g;
                afr[mi][0] = As[m * STRH + ku + tg];
                afr[mi][1] = As[(m + 8) * STRH + ku + tg];
                afr[mi][2] = As[m * STRH + ku + tg + 4];
                afr[mi][3] = As[(m + 8) * STRH + ku + tg + 4];
            }
            uint32_t bfr[8][2];
#pragma unroll
            for (int ni = 0; ni < 8; ni++) {
                int n = wn * 64 + ni * 8 + g;
                bfr[ni][0] = Bs[n * STRH + ku + tg];
                bfr[ni][1] = Bs[n * STRH + ku + tg + 4];
            }
#pragma unroll
            for (int mi = 0; mi < 4; mi++)
#pragma unroll
                for (int ni = 0; ni < 8; ni++)
                    mma_f16(acc[mi][ni], afr[mi], bfr[ni]);
        }
        __syncthreads();
    }

#pragma unroll
    for (int mi = 0; mi < 4; mi++) {
#pragma unroll
        for (int rr = 0; rr < 2; rr++) {
            int row = bm + wm * 64 + mi * 16 + rr * 8 + g;
#pragma unroll
            for (int ni = 0; ni < 8; ni++) {
                int col = bn + wn * 64 + ni * 8 + tg * 2;
                float vx = acc[mi][ni][rr * 2 + 0];
                float vy = acc[mi][ni][rr * 2 + 1];
                if (EPI & 1) { vx += bias[col]; vy += bias[col + 1]; }
                if (EPI & 4) {
                    const float* rp = res + (size_t)row * N + col;
                    vx += rp[0]; vy += rp[1];
                }
                if (EPI & 2) { vx = fmaxf(vx, 0.f); vy = fmaxf(vy, 0.f); }
                if (EPI & 8) {
                    *(__half2*)&Ch[(size_t)row * N + col] = __floats2half2_rn(vx, vy);
                } else {
                    *(float2*)&Cf[(size_t)row * N + col] = make_float2(vx, vy);
                }
            }
        }
    }
}

// ---------------------------------------------------------------------------
// Fused attention per (b, h) — fp16 MMAs + register-resident softmax.
// P overwrites the QK accumulator in place.
// ---------------------------------------------------------------------------
#define QH_STR 36
#define KH_STR 36
#define VT_STR 60
#define QH_OFF 0
#define KH_OFF (QH_OFF + 112 * QH_STR)
#define VT_OFF (KH_OFF + 112 * KH_STR)
#define ATT_U32 (VT_OFF + 64 * VT_STR)
#define ATT_SMEM (ATT_U32 * 4)   // 47616 bytes

__global__ __launch_bounds__(256)
void attention_kernel(const __half* __restrict__ QKV, __half* __restrict__ ctx) {
    extern __shared__ uint32_t su[];
    uint32_t* qh = su + QH_OFF;
    uint32_t* kh = su + KH_OFF;
    uint32_t* vt = su + VT_OFF;
    __half* vth = (__half*)vt;

    int bh = blockIdx.x;
    int b = bh / H_;
    int h = bh % H_;
    int tid = threadIdx.x;
    int lane = tid & 31, warp = tid >> 5;
    int g = lane >> 2, tg = lane & 3;

    for (int i = tid; i < 64 * VT_STR; i += 256) vt[i] = 0;
    __syncthreads();

    for (int i = tid; i < S_ * 16; i += 256) {
        int s = i >> 4, e4 = (i & 15) * 4;
        size_t off = ((size_t)(b * S_ + s)) * N_QKV + h * DEPTH_ + e4;
        qh[s * QH_STR + e4 / 2] = *(const uint32_t*)(QKV + off);
        qh[s * QH_STR + e4 / 2 + 1] = *(const uint32_t*)(QKV + off + 2);
        kh[s * KH_STR + e4 / 2] = *(const uint32_t*)(QKV + off + D_);
        kh[s * KH_STR + e4 / 2 + 1] = *(const uint32_t*)(QKV + off + D_ + 2);
        __half2 v01 = *(const __half2*)(QKV + off + 2 * D_);
        __half2 v23 = *(const __half2*)(QKV + off + 2 * D_ + 2);
        vth[(e4 + 0) * (VT_STR * 2) + s] = __low2half(v01);
        vth[(e4 + 1) * (VT_STR * 2) + s] = __high2half(v01);
        vth[(e4 + 2) * (VT_STR * 2) + s] = __low2half(v23);
        vth[(e4 + 3) * (VT_STR * 2) + s] = __high2half(v23);
    }
    __syncthreads();

    if (warp >= 7) return;

    // QK^T
    float acc[13][4];
#pragma unroll
    for (int ni = 0; ni < 13; ni++)
#pragma unroll
        for (int c = 0; c < 4; c++) acc[ni][c] = 0.f;
    {
        int m = warp * 16 + g;
#pragma unroll
        for (int ks = 0; ks < 4; ks++) {
            int ku = ks * 8;
            uint32_t a[4];
            a[0] = qh[m * QH_STR + ku + tg];
            a[1] = qh[(m + 8) * QH_STR + ku + tg];
            a[2] = qh[m * QH_STR + ku + tg + 4];
            a[3] = qh[(m + 8) * QH_STR + ku + tg + 4];
#pragma unroll
            for (int ni = 0; ni < 13; ni++) {
                int n = ni * 8 + g;
                uint32_t bf[2];
                bf[0] = kh[n * KH_STR + ku + tg];
                bf[1] = kh[n * KH_STR + ku + tg + 4];
                mma_f16(acc[ni], a, bf);
            }
        }
    }

    // Register softmax (in place: acc becomes P).
    const float scale = 0.125f;
#pragma unroll
    for (int rr = 0; rr < 2; rr++) {
        float m = -1e30f;
#pragma unroll
        for (int ni = 0; ni < 13; ni++)
#pragma unroll
            for (int j = 0; j < 2; j++) {
                int col = ni * 8 + 2 * tg + j;
                if (col < S_) m = fmaxf(m, acc[ni][rr * 2 + j] * scale);
            }
        m = fmaxf(m, __shfl_xor_sync(0xffffffffu, m, 1));
        m = fmaxf(m, __shfl_xor_sync(0xffffffffu, m, 2));
        float sum = 0.f;
#pragma unroll
        for (int ni = 0; ni < 13; ni++)
#pragma unroll
            for (int j = 0; j < 2; j++) {
                int col = ni * 8 + 2 * tg + j;
                float e = 0.f;
                if (col < S_) e = __expf(acc[ni][rr * 2 + j] * scale - m);
                acc[ni][rr * 2 + j] = e;
                sum += e;
            }
        sum += __shfl_xor_sync(0xffffffffu, sum, 1);
        sum += __shfl_xor_sync(0xffffffffu, sum, 2);
        float inv = 1.f / sum;
#pragma unroll
        for (int ni = 0; ni < 13; ni++) {
            acc[ni][rr * 2 + 0] *= inv;
            acc[ni][rr * 2 + 1] *= inv;
        }
    }

    // AV
    float oacc[8][4];
#pragma unroll
    for (int ni = 0; ni < 8; ni++)
#pragma unroll
        for (int c = 0; c < 4; c++) oacc[ni][c] = 0.f;
#pragma unroll
    for (int ks = 0; ks < 7; ks++) {
        uint32_t a[4];
        __half2 h0 = __floats2half2_rn(acc[2 * ks][0], acc[2 * ks][1]);
        __half2 h1 = __floats2half2_rn(acc[2 * ks][2], acc[2 * ks][3]);
        a[0] = *(uint32_t*)&h0;
        a[1] = *(uint32_t*)&h1;
        if (ks < 6) {
            __half2 h2 = __floats2half2_rn(acc[2 * ks + 1][0], acc[2 * ks + 1][1]);
            __half2 h3 = __floats2half2_rn(acc[2 * ks + 1][2], acc[2 * ks + 1][3]);
            a[2] = *(uint32_t*)&h2;
            a[3] = *(uint32_t*)&h3;
        } else {
            a[2] = 0;
            a[3] = 0;
        }
        int ku = ks * 8;
#pragma unroll
        for (int ni = 0; ni < 8; ni++) {
            int n = ni * 8 + g;
            uint32_t bf[2];
            bf[0] = vt[n * VT_STR + ku + tg];
            bf[1] = vt[n * VT_STR + ku + tg + 4];
            mma_f16(oacc[ni], a, bf);
        }
    }

    const size_t cbase = (size_t)b * S_ * D_ + (size_t)h * DEPTH_;
#pragma unroll
    for (int ni = 0; ni < 8; ni++)
#pragma unroll
        for (int rr = 0; rr < 2; rr++) {
            int row = warp * 16 + rr * 8 + g;
            if (row < S_) {
                int col = ni * 8 + tg * 2;
                *(__half2*)&ctx[cbase + (size_t)row * D_ + col] =
                    __floats2half2_rn(oacc[ni][rr * 2], oacc[ni][rr * 2 + 1]);
            }
        }
}

// ---------------------------------------------------------------------------
// Fused split-K reduce + bias + residual + LayerNorm (optional fp16 twin).
// ---------------------------------------------------------------------------
template <bool HALF2>
__global__ __launch_bounds__(256)
void lnred_kernel(const float* __restrict__ p0, const float* __restrict__ p1,
                  const float* __restrict__ bias, const float* __restrict__ res,
                  const float* __restrict__ gamma, const float* __restrict__ beta,
                  float* __restrict__ out, __half* __restrict__ out_h) {
    int row = blockIdx.x;
    size_t base = (size_t)row * D_;
    int tid = threadIdx.x;

    float vals[4];
    float sum = 0.f, sq = 0.f;
#pragma unroll
    for (int r = 0; r < 4; r++) {
        int d = tid + r * 256;
        float v = p0[base + d] + p1[base + d] + bias[d] + res[base + d];
        vals[r] = v;
        sum += v;
        sq += v * v;
    }
#pragma unroll
    for (int off = 16; off > 0; off >>= 1) {
        sum += __shfl_xor_sync(0xffffffffu, sum, off);
        sq += __shfl_xor_sync(0xffffffffu, sq, off);
    }
    __shared__ float s1[8], s2[8];
    int wid = tid >> 5, lid = tid & 31;
    if (lid == 0) { s1[wid] = sum; s2[wid] = sq; }
    __syncthreads();
    if (wid == 0) {
        sum = (lid < 8) ? s1[lid] : 0.f;
        sq = (lid < 8) ? s2[lid] : 0.f;
#pragma unroll
        for (int off = 4; off > 0; off >>= 1) {
            sum += __shfl_xor_sync(0xffffffffu, sum, off);
            sq += __shfl_xor_sync(0xffffffffu, sq, off);
        }
        if (lid == 0) { s1[0] = sum; s2[0] = sq; }
    }
    __syncthreads();
    float mean = s1[0] * (1.0f / D_);
    float var = s2[0] * (1.0f / D_) - mean * mean;
    float inv = rsqrtf(var + EPS_);
#pragma unroll
    for (int r = 0; r < 4; r++) {
        int d = tid + r * 256;
        float o = gamma[d] * ((vals[r] - mean) * inv) + beta[d];
        out[base + d] = o;
        if (HALF2) out_h[base + d] = __float2half_rn(o);
    }
}

// ---------------------------------------------------------------------------
// Launch
// ---------------------------------------------------------------------------
extern "C" void kernel_launch(void* const* d_in, const int* in_sizes, int n_in,
                              void* d_out, int out_size) {
    const int* tokens = (const int*)d_in[0];
    const float* emb = (const float*)d_in[1];
    const float* Wq = (const float*)d_in[2];
    const float* bq = (const float*)d_in[3];
    const float* Wk = (const float*)d_in[4];
    const float* bk = (const float*)d_in[5];
    const float* Wv = (const float*)d_in[6];
    const float* bv = (const float*)d_in[7];
    const float* Wo = (const float*)d_in[8];
    const float* bo = (const float*)d_in[9];
    const float* W1 = (const float*)d_in[10];
    const float* b1 = (const float*)d_in[11];
    const float* W2 = (const float*)d_in[12];
    const float* b2 = (const float*)d_in[13];
    const float* gamma1 = (const float*)d_in[14];
    const float* beta1 = (const float*)d_in[15];
    const float* gamma2 = (const float*)d_in[16];
    const float* beta2 = (const float*)d_in[17];
    float* out = (float*)d_out;

    float *pe, *x, *bqkv, *t1, *x1;
    __half *xh, *WqkvTh, *WoTh, *W1Th, *W2Th, *QKVh, *ctxh, *x1h, *ffhh;
    cudaGetSymbolAddress((void**)&pe, g_pe);
    cudaGetSymbolAddress((void**)&x, g_x);
    cudaGetSymbolAddress((void**)&xh, g_xh);
    cudaGetSymbolAddress((void**)&WqkvTh, g_WqkvTh);
    cudaGetSymbolAddress((void**)&bqkv, g_bqkv);
    cudaGetSymbolAddress((void**)&WoTh, g_WoTh);
    cudaGetSymbolAddress((void**)&W1Th, g_W1Th);
    cudaGetSymbolAddress((void**)&W2Th, g_W2Th);
    cudaGetSymbolAddress((void**)&QKVh, g_QKVh);
    cudaGetSymbolAddress((void**)&ctxh, g_ctxh);
    cudaGetSymbolAddress((void**)&t1, g_t1);
    cudaGetSymbolAddress((void**)&x1, g_x1);
    cudaGetSymbolAddress((void**)&x1h, g_x1h);
    cudaGetSymbolAddress((void**)&ffhh, g_ffhh);

    cudaFuncSetAttribute(attention_kernel,
                         cudaFuncAttributeMaxDynamicSharedMemorySize, ATT_SMEM);
    cudaFuncSetAttribute(mma_gemm_h<0>,
                         cudaFuncAttributeMaxDynamicSharedMemorySize, SMEM_GEMM);
    cudaFuncSetAttribute(mma_gemm_h<9>,
                         cudaFuncAttributeMaxDynamicSharedMemorySize, SMEM_GEMM);
    cudaFuncSetAttribute(mma_gemm_h<11>,
                         cudaFuncAttributeMaxDynamicSharedMemorySize, SMEM_GEMM);

    // 0-1. positional encoding + embedding (+ bias concat folded in)
    pe_kernel<<<(S_ * D_ + 255) / 256, 256>>>(pe);
    embed_kernel<<<(BS_ * D_ / 4 + 255) / 256, 256>>>(tokens, emb, pe, x, xh,
                                                      bq, bk, bv, bqkv);

    // 2-3. weight prep (merged transposes)
    qkvT_kernel<<<dim3(2, 32, 48), dim3(32, 8)>>>(Wq, Wk, Wv, WqkvTh);
    transpose_all<<<9216, dim3(32, 8)>>>(Wo, WoTh, W1, W1Th, W2, W2Th);

    // 4. fused QKV projection (bias + fp16 output)
    mma_gemm_h<9><<<dim3(N_QKV / 128, BS_ / 128), 128, SMEM_GEMM>>>(
        xh, WqkvTh, QKVh, bqkv, nullptr, BS_, N_QKV, D_);

    // 5. attention (fp16 MMA, register softmax)
    attention_kernel<<<B_ * H_, 256, ATT_SMEM>>>(QKVh, ctxh);

    // 6-7. output projection (split-K 2) + fused reduce+LN1
    mma_gemm_h<0><<<dim3(D_ / 128, BS_ / 128, 2), 128, SMEM_GEMM>>>(
        ctxh, WoTh, t1, nullptr, nullptr, BS_, D_, D_);
    lnred_kernel<true><<<BS_, 256>>>(t1, t1 + (size_t)BS_ * D_, bo, x,
                                     gamma1, beta1, x1, x1h);

    // 8-9. FFN
    mma_gemm_h<11><<<dim3(F_ / 128, BS_ / 128), 128, SMEM_GEMM>>>(
        x1h, W1Th, ffhh, b1, nullptr, BS_, F_, D_);
    mma_gemm_h<0><<<dim3(D_ / 128, BS_ / 128, 2), 128, SMEM_GEMM>>>(
        ffhh, W2Th, t1, nullptr, nullptr, BS_, D_, F_);

    // 10. fused reduce + LN2 -> output
    lnred_kernel<false><<<BS_, 256>>>(t1, t1 + (size_t)BS_ * D_, b2, x1,
                                      gamma2, beta2, out, nullptr);
}